// round 7
// baseline (speedup 1.0000x reference)
#include <cuda_runtime.h>
#include <math.h>

// Problem constants
#define Bb    8
#define Ll    2048
#define Vv    51919
#define Ee    100
#define Ff    256
#define KW    9
#define Yy    8921
#define YTILES 140
#define US    260       // Usm row stride (floats): mult of 4 (alignment), rows+4 -> distinct bank groups

// Device scratch (no cudaMalloc allowed)
__device__ float g_wT[Ee*KW*Ff];          // conv weights transposed: [(e*K+k)][f]
__device__ float g_h[(size_t)Bb*Ll*Ff];   // conv output h: [b][l][f]
__device__ float g_part[256];             // loss partials

// ---------------------------------------------------------------------------
// K0: transpose conv_w [F,E,K] -> g_wT [(E*K), F]
// ---------------------------------------------------------------------------
__global__ void k_transpose(const float* __restrict__ w)
{
    int idx = blockIdx.x * 256 + threadIdx.x;
    if (idx < Ff*Ee*KW) {
        int f = idx / (Ee*KW);
        int r = idx - f*(Ee*KW);
        g_wT[r*Ff + f] = w[idx];
    }
}

// ---------------------------------------------------------------------------
// K1: embedding gather + conv1d(K=9, same pad) + bias + tanh -> g_h [b][l][f]
// ---------------------------------------------------------------------------
__global__ __launch_bounds__(256) void k_conv(const int* __restrict__ x,
                                              const float* __restrict__ embW,
                                              const float* __restrict__ convb)
{
    __shared__ int   toks[24];
    __shared__ float semb[24][Ee];

    int tid = threadIdx.x;
    int b   = blockIdx.y;
    int l0  = blockIdx.x * 16;

    if (tid < 24) {
        int l = l0 - 4 + tid;
        toks[tid] = (l >= 0 && l < Ll) ? x[b*Ll + l] : -1;
    }
    __syncthreads();

    for (int idx = tid; idx < 24*Ee; idx += 256) {
        int t = idx / Ee;
        int c = idx - t*Ee;
        int tok = toks[t];
        semb[t][c] = (tok >= 0) ? embW[(size_t)tok*Ee + c] : 0.f;
    }
    __syncthreads();

    int f = tid;
    float acc[16];
#pragma unroll
    for (int j = 0; j < 16; j++) acc[j] = 0.f;

    for (int e = 0; e < Ee; e++) {
        float r[24];
#pragma unroll
        for (int t = 0; t < 24; t++) r[t] = semb[t][e];
#pragma unroll
        for (int k = 0; k < KW; k++) {
            float w = g_wT[(e*KW + k)*Ff + f];
#pragma unroll
            for (int j = 0; j < 16; j++)
                acc[j] = fmaf(w, r[j + k], acc[j]);
        }
    }

    float bias = convb[f];
    float* hp = g_h + ((size_t)b*Ll + l0)*Ff + f;
#pragma unroll
    for (int j = 0; j < 16; j++)
        hp[(size_t)j*Ff] = tanhf(acc[j] + bias);
}

// ---------------------------------------------------------------------------
// K2: FUSED attention per (batch, 64-label tile), single pass over L.
//   h tile stored as XOR-swizzled float4 slots: slot(r,c4) = r*64 + (c4 ^ ((r>>2)&7))
//   -> conflict-free LDS.128 in both GEMM phases (quarter-warp wavefronts).
//   m-GEMM per-thread f-tile: f = fi*64 + tl*4 + j  (4 x float4 at chunk fi*16+tl)
// NOTE: alpha region of d_out starts at element B*Y+1 (NOT 16B-aligned)
//       -> all global accesses there are scalar (4B) but coalesced.
// ---------------------------------------------------------------------------
#define SM_FLOATS (64*US + 64*256 + 64*64 + 64*16 + 64)
#define SM_BYTES  (SM_FLOATS * 4)

__global__ __launch_bounds__(256) void k_attn(const float* __restrict__ Uw,
                                              const float* __restrict__ fw,
                                              const float* __restrict__ fb,
                                              float* __restrict__ out)
{
    extern __shared__ float sm[];
    float*  Usm     = sm;                    // [64][US]
    float4* hsm4    = (float4*)(sm + 64*US); // [64 rows][64 slots] swizzled
    float*  esm     = sm + 64*US + 64*256;   // [64][64]
    float*  red     = esm + 64*64;           // [64][16]
    float*  rowsums = red + 64*16;           // [64]

    int tid = threadIdx.x;
    int ty  = tid >> 4;       // 0..15 -> 4 y's each
    int tl  = tid & 15;       // 0..15
    int b   = blockIdx.y;
    int ybase = blockIdx.x * 64;

    // Load U tile (zero-fill beyond Y)
    for (int idx = tid; idx < 64*256; idx += 256) {
        int r = idx >> 8, c = idx & 255;
        int gy = ybase + r;
        Usm[r*US + c] = (gy < Yy) ? Uw[(size_t)gy*Ff + c] : 0.f;
    }

    float macc[4][16];
#pragma unroll
    for (int yi = 0; yi < 4; yi++)
#pragma unroll
        for (int fi = 0; fi < 16; fi++) macc[yi][fi] = 0.f;
    float rsum[4] = {0.f, 0.f, 0.f, 0.f};
    __syncthreads();

    const float* hbase = g_h + (size_t)b*Ll*Ff;
    // out layout: yhat [B*Y], loss [1], alpha [B][Y][L]
    float* alpha = out + (size_t)Bb*Yy + 1;
    float* ablk  = alpha + ((size_t)b*Yy + ybase)*Ll;

    for (int lc = 0; lc < Ll/64; lc++) {
        // load h tile [64 l][256 f] with xor swizzle on float4 slots
        const float4* hp4 = (const float4*)(hbase + (size_t)lc*64*Ff);
        for (int idx = tid; idx < 64*64; idx += 256) {
            int r = idx >> 6, c4 = idx & 63;
            hsm4[r*64 + (c4 ^ ((r >> 2) & 7))] = hp4[r*64 + c4];
        }
        __syncthreads();

        // ---- s-GEMM 4y x 4l ----
        float acc[4][4];
#pragma unroll
        for (int i = 0; i < 4; i++)
#pragma unroll
            for (int j = 0; j < 4; j++) acc[i][j] = 0.f;

#pragma unroll 4
        for (int k4 = 0; k4 < 64; k4++) {
            int sw = k4 ^ (tl & 7);     // swizzle term: (tl*4+li)>>2 == tl for li<4
            float4 bv[4];
#pragma unroll
            for (int li = 0; li < 4; li++)
                bv[li] = hsm4[(tl*4 + li)*64 + sw];
            float4 av[4];
#pragma unroll
            for (int yi = 0; yi < 4; yi++)
                av[yi] = *(const float4*)&Usm[(ty*4 + yi)*US + k4*4];
#pragma unroll
            for (int yi = 0; yi < 4; yi++)
#pragma unroll
                for (int li = 0; li < 4; li++) {
                    acc[yi][li] = fmaf(av[yi].x, bv[li].x, acc[yi][li]);
                    acc[yi][li] = fmaf(av[yi].y, bv[li].y, acc[yi][li]);
                    acc[yi][li] = fmaf(av[yi].z, bv[li].z, acc[yi][li]);
                    acc[yi][li] = fmaf(av[yi].w, bv[li].w, acc[yi][li]);
                }
        }

        // ---- e = exp(s); rowsum; stash to esm ----
#pragma unroll
        for (int yi = 0; yi < 4; yi++) {
            int y = ty*4 + yi;
            float4 ev;
            ev.x = __expf(acc[yi][0]);
            ev.y = __expf(acc[yi][1]);
            ev.z = __expf(acc[yi][2]);
            ev.w = __expf(acc[yi][3]);
            rsum[yi] += ev.x + ev.y + ev.z + ev.w;
            *(float4*)&esm[y*64 + tl*4] = ev;
        }
        __syncthreads();

        // ---- coalesced SCALAR stream of e to gmem (alpha base misaligned) ----
        for (int idx = tid; idx < 64*64; idx += 256) {
            int y = idx >> 6, l = idx & 63;
            if (ybase + y < Yy)
                ablk[(size_t)y*Ll + lc*64 + l] = esm[idx];
        }

        // ---- m-GEMM: macc[y][fi*4+j] += e[y][l] * h[l][fi*64+tl*4+j] ----
#pragma unroll 2
        for (int l = 0; l < 64; l++) {
            int x = (l >> 2) & 7;
            const float4* hrow = hsm4 + l*64;
            int t = tl ^ x;
            float4 h0 = hrow[t];
            float4 h1 = hrow[16 + t];
            float4 h2 = hrow[32 + t];
            float4 h3 = hrow[48 + t];
            float evv[4];
#pragma unroll
            for (int yi = 0; yi < 4; yi++) evv[yi] = esm[(ty*4 + yi)*64 + l];
#pragma unroll
            for (int yi = 0; yi < 4; yi++) {
                float e = evv[yi];
                macc[yi][0]  = fmaf(e, h0.x, macc[yi][0]);
                macc[yi][1]  = fmaf(e, h0.y, macc[yi][1]);
                macc[yi][2]  = fmaf(e, h0.z, macc[yi][2]);
                macc[yi][3]  = fmaf(e, h0.w, macc[yi][3]);
                macc[yi][4]  = fmaf(e, h1.x, macc[yi][4]);
                macc[yi][5]  = fmaf(e, h1.y, macc[yi][5]);
                macc[yi][6]  = fmaf(e, h1.z, macc[yi][6]);
                macc[yi][7]  = fmaf(e, h1.w, macc[yi][7]);
                macc[yi][8]  = fmaf(e, h2.x, macc[yi][8]);
                macc[yi][9]  = fmaf(e, h2.y, macc[yi][9]);
                macc[yi][10] = fmaf(e, h2.z, macc[yi][10]);
                macc[yi][11] = fmaf(e, h2.w, macc[yi][11]);
                macc[yi][12] = fmaf(e, h3.x, macc[yi][12]);
                macc[yi][13] = fmaf(e, h3.y, macc[yi][13]);
                macc[yi][14] = fmaf(e, h3.z, macc[yi][14]);
                macc[yi][15] = fmaf(e, h3.w, macc[yi][15]);
            }
        }
        __syncthreads();
    }

    // rowsum reduce across the 16 tl threads per y
#pragma unroll
    for (int yi = 0; yi < 4; yi++) red[(ty*4 + yi)*16 + tl] = rsum[yi];
    __syncthreads();
    if (tid < 64) {
        float s = 0.f;
#pragma unroll
        for (int i = 0; i < 16; i++) s += red[tid*16 + i];
        rowsums[tid] = s;
    }
    __syncthreads();

    // ---------------- yhat ----------------
    // thread's f-tile: f = fi*64 + tl*4 + j  -> fw chunk index fi*16 + tl
#pragma unroll
    for (int yi = 0; yi < 4; yi++) {
        int y = ty*4 + yi;
        int gy = ybase + y;
        float p = 0.f;
        if (gy < Yy) {
            const float4* fw4 = (const float4*)(fw + (size_t)gy*Ff);
#pragma unroll
            for (int fi = 0; fi < 4; fi++) {
                float4 w = fw4[fi*16 + tl];
                p = fmaf(w.x, macc[yi][fi*4+0], p);
                p = fmaf(w.y, macc[yi][fi*4+1], p);
                p = fmaf(w.z, macc[yi][fi*4+2], p);
                p = fmaf(w.w, macc[yi][fi*4+3], p);
            }
        }
        red[y*16 + tl] = p;
    }
    __syncthreads();
    if (tid < 64) {
        int gy = ybase + tid;
        if (gy < Yy) {
            float s = 0.f;
#pragma unroll
            for (int i = 0; i < 16; i++) s += red[tid*16 + i];
            out[(size_t)b*Yy + gy] = s / rowsums[tid] + fb[gy];
        }
    }
    __syncthreads();

    // ---------------- alpha rescale: alpha = e / Z (scalar, coalesced) -------
    for (int y = 0; y < 64; y++) {
        int gy = ybase + y;
        if (gy >= Yy) break;
        float inv = 1.f / rowsums[y];
        float* row = ablk + (size_t)y*Ll;
        for (int l = tid; l < Ll; l += 256)
            row[l] *= inv;
    }
}

// ---------------------------------------------------------------------------
// K3: BCE loss, two-stage deterministic reduction
// ---------------------------------------------------------------------------
__global__ void k_loss1(const float* __restrict__ target, const float* __restrict__ out)
{
    __shared__ float red[256];
    int tid = threadIdx.x;
    float s = 0.f;
    for (int i = blockIdx.x*256 + tid; i < Bb*Yy; i += gridDim.x*256) {
        float yh = out[i];
        float t  = target[i];
        s += fmaxf(yh, 0.f) - yh*t + log1pf(__expf(-fabsf(yh)));
    }
    red[tid] = s;
    __syncthreads();
    for (int st = 128; st > 0; st >>= 1) {
        if (tid < st) red[tid] += red[tid + st];
        __syncthreads();
    }
    if (tid == 0) g_part[blockIdx.x] = red[0];
}

__global__ void k_loss2(float* __restrict__ out)
{
    __shared__ float red[128];
    int tid = threadIdx.x;
    red[tid] = (tid < 70) ? g_part[tid] : 0.f;
    __syncthreads();
    for (int st = 64; st > 0; st >>= 1) {
        if (tid < st) red[tid] += red[tid + st];
        __syncthreads();
    }
    if (tid == 0) out[Bb*Yy] = red[0] / (float)(Bb*Yy);
}

// ---------------------------------------------------------------------------
extern "C" void kernel_launch(void* const* d_in, const int* in_sizes, int n_in,
                              void* d_out, int out_size)
{
    const int*   x      = (const int*)d_in[0];
    const float* target = (const float*)d_in[1];
    const float* embW   = (const float*)d_in[2];
    const float* convw  = (const float*)d_in[3];
    const float* convb  = (const float*)d_in[4];
    const float* Uw     = (const float*)d_in[5];
    const float* fw     = (const float*)d_in[6];
    const float* fb     = (const float*)d_in[7];
    float* out = (float*)d_out;

    cudaFuncSetAttribute(k_attn, cudaFuncAttributeMaxDynamicSharedMemorySize, SM_BYTES);

    k_transpose<<<(Ff*Ee*KW + 255)/256, 256>>>(convw);
    k_conv<<<dim3(Ll/16, Bb), 256>>>(x, embW, convb);
    k_attn<<<dim3(YTILES, Bb), 256, SM_BYTES>>>(Uw, fw, fb, out);
    k_loss1<<<70, 256>>>(target, out);
    k_loss2<<<1, 128>>>(out);
}

// round 8
// speedup vs baseline: 1.0966x; 1.0966x over previous
#include <cuda_runtime.h>
#include <math.h>

// Problem constants
#define Bb    8
#define Ll    2048
#define Vv    51919
#define Ee    100
#define Ff    256
#define KW    9
#define Yy    8921
#define YTILES 140
#define US    260       // Usm row stride (floats); 260*4=1040 B = 65*16 -> float4-aligned rows

typedef unsigned long long u64;

// packed dual-lane fp32 FMA: d.lo += a.lo*b.lo ; d.hi += a.hi*b.hi
#define FFMA2(d, a, b) \
    asm("fma.rn.f32x2 %0, %1, %2, %0;" : "+l"(d) : "l"(a), "l"(b))

#define PACK2(d, s) \
    asm("mov.b64 %0, {%1, %1};" : "=l"(d) : "r"(__float_as_uint(s)))

__device__ __forceinline__ float pair_sum(u64 v) {
    unsigned lo, hi;
    asm("mov.b64 {%0, %1}, %2;" : "=r"(lo), "=r"(hi) : "l"(v));
    return __uint_as_float(lo) + __uint_as_float(hi);
}
__device__ __forceinline__ float pair_lo(u64 v) {
    unsigned lo, hi;
    asm("mov.b64 {%0, %1}, %2;" : "=r"(lo), "=r"(hi) : "l"(v));
    return __uint_as_float(lo);
}
__device__ __forceinline__ float pair_hi(u64 v) {
    unsigned lo, hi;
    asm("mov.b64 {%0, %1}, %2;" : "=r"(lo), "=r"(hi) : "l"(v));
    return __uint_as_float(hi);
}

// Device scratch (no cudaMalloc allowed)
__device__ float g_wT[Ee*KW*Ff];          // conv weights transposed: [(e*K+k)][f]
__device__ float g_h[(size_t)Bb*Ll*Ff];   // conv output h: [b][l][f]
__device__ float g_part[256];             // loss partials

// ---------------------------------------------------------------------------
// K0: transpose conv_w [F,E,K] -> g_wT [(E*K), F]
// ---------------------------------------------------------------------------
__global__ void k_transpose(const float* __restrict__ w)
{
    int idx = blockIdx.x * 256 + threadIdx.x;
    if (idx < Ff*Ee*KW) {
        int f = idx / (Ee*KW);
        int r = idx - f*(Ee*KW);
        g_wT[r*Ff + f] = w[idx];
    }
}

// ---------------------------------------------------------------------------
// K1: embedding gather + conv1d(K=9, same pad) + bias + tanh -> g_h [b][l][f]
// ---------------------------------------------------------------------------
__global__ __launch_bounds__(256) void k_conv(const int* __restrict__ x,
                                              const float* __restrict__ embW,
                                              const float* __restrict__ convb)
{
    __shared__ int   toks[24];
    __shared__ float semb[24][Ee];

    int tid = threadIdx.x;
    int b   = blockIdx.y;
    int l0  = blockIdx.x * 16;

    if (tid < 24) {
        int l = l0 - 4 + tid;
        toks[tid] = (l >= 0 && l < Ll) ? x[b*Ll + l] : -1;
    }
    __syncthreads();

    for (int idx = tid; idx < 24*Ee; idx += 256) {
        int t = idx / Ee;
        int c = idx - t*Ee;
        int tok = toks[t];
        semb[t][c] = (tok >= 0) ? embW[(size_t)tok*Ee + c] : 0.f;
    }
    __syncthreads();

    int f = tid;
    float acc[16];
#pragma unroll
    for (int j = 0; j < 16; j++) acc[j] = 0.f;

    for (int e = 0; e < Ee; e++) {
        float r[24];
#pragma unroll
        for (int t = 0; t < 24; t++) r[t] = semb[t][e];
#pragma unroll
        for (int k = 0; k < KW; k++) {
            float w = g_wT[(e*KW + k)*Ff + f];
#pragma unroll
            for (int j = 0; j < 16; j++)
                acc[j] = fmaf(w, r[j + k], acc[j]);
        }
    }

    float bias = convb[f];
    float* hp = g_h + ((size_t)b*Ll + l0)*Ff + f;
#pragma unroll
    for (int j = 0; j < 16; j++)
        hp[(size_t)j*Ff] = tanhf(acc[j] + bias);
}

// ---------------------------------------------------------------------------
// K2: FUSED attention per (batch, 64-label tile), single pass over L.
//   Inner GEMMs use packed fma.rn.f32x2 (FFMA2, 2 MAC/issue):
//     s-GEMM: pair lanes = (even k, odd k) partial sums, summed at the end
//     m-GEMM: pair lanes = adjacent f, multiplier (e,e) broadcast pair
//   h tile in XOR-swizzled float4 slots: slot(r,c4) = r*64 + (c4 ^ ((r>>2)&7))
// NOTE: alpha region of d_out starts at element B*Y+1 (NOT 16B-aligned)
//       -> all global accesses there are scalar (4B) but coalesced.
// ---------------------------------------------------------------------------
#define SM_FLOATS (64*US + 64*256 + 64*64 + 64*16 + 64)
#define SM_BYTES  (SM_FLOATS * 4)

__global__ __launch_bounds__(256) void k_attn(const float* __restrict__ Uw,
                                              const float* __restrict__ fw,
                                              const float* __restrict__ fb,
                                              float* __restrict__ out)
{
    extern __shared__ float sm[];
    float*  Usm     = sm;                    // [64][US]
    float4* hsm4    = (float4*)(sm + 64*US); // [64 rows][64 slots] swizzled
    float*  esm     = sm + 64*US + 64*256;   // [64][64]
    float*  red     = esm + 64*64;           // [64][16]
    float*  rowsums = red + 64*16;           // [64]

    int tid = threadIdx.x;
    int ty  = tid >> 4;       // 0..15 -> 4 y's each
    int tl  = tid & 15;       // 0..15
    int b   = blockIdx.y;
    int ybase = blockIdx.x * 64;

    // Load U tile (zero-fill beyond Y)
    for (int idx = tid; idx < 64*256; idx += 256) {
        int r = idx >> 8, c = idx & 255;
        int gy = ybase + r;
        Usm[r*US + c] = (gy < Yy) ? Uw[(size_t)gy*Ff + c] : 0.f;
    }

    u64 macc2[4][8];   // pair over adjacent f; f = fi*64 + tl*4 + (0..3)
#pragma unroll
    for (int yi = 0; yi < 4; yi++)
#pragma unroll
        for (int fp = 0; fp < 8; fp++) macc2[yi][fp] = 0ULL;
    float rsum[4] = {0.f, 0.f, 0.f, 0.f};
    __syncthreads();

    const float* hbase = g_h + (size_t)b*Ll*Ff;
    // out layout: yhat [B*Y], loss [1], alpha [B][Y][L]
    float* alpha = out + (size_t)Bb*Yy + 1;
    float* ablk  = alpha + ((size_t)b*Yy + ybase)*Ll;

    for (int lc = 0; lc < Ll/64; lc++) {
        // load h tile [64 l][256 f] with xor swizzle on float4 slots
        const float4* hp4 = (const float4*)(hbase + (size_t)lc*64*Ff);
        for (int idx = tid; idx < 64*64; idx += 256) {
            int r = idx >> 6, c4 = idx & 63;
            hsm4[r*64 + (c4 ^ ((r >> 2) & 7))] = hp4[r*64 + c4];
        }
        __syncthreads();

        // ---- s-GEMM 4y x 4l, FFMA2 over (even k, odd k) lanes ----
        u64 acc2[4][4];
#pragma unroll
        for (int i = 0; i < 4; i++)
#pragma unroll
            for (int j = 0; j < 4; j++) acc2[i][j] = 0ULL;

        const ulonglong2* hs2 = (const ulonglong2*)hsm4;
#pragma unroll 4
        for (int k4 = 0; k4 < 64; k4++) {
            int sw = k4 ^ (tl & 7);     // swizzle term: (tl*4+li)>>2 == tl for li<4
            u64 b0[4], b1[4];
#pragma unroll
            for (int li = 0; li < 4; li++) {
                ulonglong2 bv = hs2[(tl*4 + li)*64 + sw];
                b0[li] = bv.x;  b1[li] = bv.y;
            }
            u64 a0[4], a1[4];
#pragma unroll
            for (int yi = 0; yi < 4; yi++) {
                ulonglong2 av = *(const ulonglong2*)&Usm[(ty*4 + yi)*US + k4*4];
                a0[yi] = av.x;  a1[yi] = av.y;
            }
#pragma unroll
            for (int yi = 0; yi < 4; yi++)
#pragma unroll
                for (int li = 0; li < 4; li++) {
                    FFMA2(acc2[yi][li], a0[yi], b0[li]);
                    FFMA2(acc2[yi][li], a1[yi], b1[li]);
                }
        }

        // ---- e = exp(s); rowsum; stash to esm ----
#pragma unroll
        for (int yi = 0; yi < 4; yi++) {
            int y = ty*4 + yi;
            float4 ev;
            ev.x = __expf(pair_sum(acc2[yi][0]));
            ev.y = __expf(pair_sum(acc2[yi][1]));
            ev.z = __expf(pair_sum(acc2[yi][2]));
            ev.w = __expf(pair_sum(acc2[yi][3]));
            rsum[yi] += ev.x + ev.y + ev.z + ev.w;
            *(float4*)&esm[y*64 + tl*4] = ev;
        }
        __syncthreads();

        // ---- coalesced SCALAR stream of e to gmem (alpha base misaligned) ----
        for (int idx = tid; idx < 64*64; idx += 256) {
            int y = idx >> 6, l = idx & 63;
            if (ybase + y < Yy)
                ablk[(size_t)y*Ll + lc*64 + l] = esm[idx];
        }

        // ---- m-GEMM: macc2[y][.] += (e,e) * h-pairs ----
#pragma unroll 2
        for (int l = 0; l < 64; l++) {
            int x = (l >> 2) & 7;
            const ulonglong2* hrow = hs2 + l*64;
            int t = tl ^ x;
            ulonglong2 H0 = hrow[t];
            ulonglong2 H1 = hrow[16 + t];
            ulonglong2 H2 = hrow[32 + t];
            ulonglong2 H3 = hrow[48 + t];
#pragma unroll
            for (int yi = 0; yi < 4; yi++) {
                u64 ep;
                PACK2(ep, esm[(ty*4 + yi)*64 + l]);
                FFMA2(macc2[yi][0], ep, H0.x);
                FFMA2(macc2[yi][1], ep, H0.y);
                FFMA2(macc2[yi][2], ep, H1.x);
                FFMA2(macc2[yi][3], ep, H1.y);
                FFMA2(macc2[yi][4], ep, H2.x);
                FFMA2(macc2[yi][5], ep, H2.y);
                FFMA2(macc2[yi][6], ep, H3.x);
                FFMA2(macc2[yi][7], ep, H3.y);
            }
        }
        __syncthreads();
    }

    // rowsum reduce across the 16 tl threads per y
#pragma unroll
    for (int yi = 0; yi < 4; yi++) red[(ty*4 + yi)*16 + tl] = rsum[yi];
    __syncthreads();
    if (tid < 64) {
        float s = 0.f;
#pragma unroll
        for (int i = 0; i < 16; i++) s += red[tid*16 + i];
        rowsums[tid] = s;
    }
    __syncthreads();

    // ---------------- yhat ----------------
    // thread's f-tile: f = fi*64 + tl*4 + j  -> fw chunk index fi*16 + tl
    // macc2[yi][2*fi]   = (m[f+0], m[f+1]) ; macc2[yi][2*fi+1] = (m[f+2], m[f+3])
#pragma unroll
    for (int yi = 0; yi < 4; yi++) {
        int y = ty*4 + yi;
        int gy = ybase + y;
        float p = 0.f;
        if (gy < Yy) {
            const float4* fw4 = (const float4*)(fw + (size_t)gy*Ff);
#pragma unroll
            for (int fi = 0; fi < 4; fi++) {
                float4 w = fw4[fi*16 + tl];
                p = fmaf(w.x, pair_lo(macc2[yi][2*fi]),   p);
                p = fmaf(w.y, pair_hi(macc2[yi][2*fi]),   p);
                p = fmaf(w.z, pair_lo(macc2[yi][2*fi+1]), p);
                p = fmaf(w.w, pair_hi(macc2[yi][2*fi+1]), p);
            }
        }
        red[y*16 + tl] = p;
    }
    __syncthreads();
    if (tid < 64) {
        int gy = ybase + tid;
        if (gy < Yy) {
            float s = 0.f;
#pragma unroll
            for (int i = 0; i < 16; i++) s += red[tid*16 + i];
            out[(size_t)b*Yy + gy] = s / rowsums[tid] + fb[gy];
        }
    }
    __syncthreads();

    // ---------------- alpha rescale: alpha = e / Z (scalar, coalesced) -------
    for (int y = 0; y < 64; y++) {
        int gy = ybase + y;
        if (gy >= Yy) break;
        float inv = 1.f / rowsums[y];
        float* row = ablk + (size_t)y*Ll;
        for (int l = tid; l < Ll; l += 256)
            row[l] *= inv;
    }
}

// ---------------------------------------------------------------------------
// K3: BCE loss, two-stage deterministic reduction
// ---------------------------------------------------------------------------
__global__ void k_loss1(const float* __restrict__ target, const float* __restrict__ out)
{
    __shared__ float red[256];
    int tid = threadIdx.x;
    float s = 0.f;
    for (int i = blockIdx.x*256 + tid; i < Bb*Yy; i += gridDim.x*256) {
        float yh = out[i];
        float t  = target[i];
        s += fmaxf(yh, 0.f) - yh*t + log1pf(__expf(-fabsf(yh)));
    }
    red[tid] = s;
    __syncthreads();
    for (int st = 128; st > 0; st >>= 1) {
        if (tid < st) red[tid] += red[tid + st];
        __syncthreads();
    }
    if (tid == 0) g_part[blockIdx.x] = red[0];
}

__global__ void k_loss2(float* __restrict__ out)
{
    __shared__ float red[128];
    int tid = threadIdx.x;
    red[tid] = (tid < 70) ? g_part[tid] : 0.f;
    __syncthreads();
    for (int st = 64; st > 0; st >>= 1) {
        if (tid < st) red[tid] += red[tid + st];
        __syncthreads();
    }
    if (tid == 0) out[Bb*Yy] = red[0] / (float)(Bb*Yy);
}

// ---------------------------------------------------------------------------
extern "C" void kernel_launch(void* const* d_in, const int* in_sizes, int n_in,
                              void* d_out, int out_size)
{
    const int*   x      = (const int*)d_in[0];
    const float* target = (const float*)d_in[1];
    const float* embW   = (const float*)d_in[2];
    const float* convw  = (const float*)d_in[3];
    const float* convb  = (const float*)d_in[4];
    const float* Uw     = (const float*)d_in[5];
    const float* fw     = (const float*)d_in[6];
    const float* fb     = (const float*)d_in[7];
    float* out = (float*)d_out;

    cudaFuncSetAttribute(k_attn, cudaFuncAttributeMaxDynamicSharedMemorySize, SM_BYTES);

    k_transpose<<<(Ff*Ee*KW + 255)/256, 256>>>(convw);
    k_conv<<<dim3(Ll/16, Bb), 256>>>(x, embW, convb);
    k_attn<<<dim3(YTILES, Bb), 256, SM_BYTES>>>(Uw, fw, fb, out);
    k_loss1<<<70, 256>>>(target, out);
    k_loss2<<<1, 128>>>(out);
}

// round 10
// speedup vs baseline: 2.1451x; 1.9561x over previous
#include <cuda_runtime.h>
#include <cuda_bf16.h>
#include <math.h>
#include <stdint.h>

// Problem constants
#define Bb    8
#define Ll    2048
#define Ee    100
#define Ff    256
#define KW    9
#define Yy    8921
#define YT    70          // ceil(8921 / 128)

typedef unsigned int u32;

// ---------------------------------------------------------------------------
// Device scratch
// ---------------------------------------------------------------------------
__device__ float          g_wT[Ee*KW*Ff];                 // conv weights [(e*K+k)][f]
__device__ __nv_bfloat16  g_hb [(size_t)Bb*Ll*Ff];        // h  hi  [b][l][f]
__device__ __nv_bfloat16  g_thi[(size_t)Bb*Ff*Ll];        // h^T hi [b][f][l]
__device__ __nv_bfloat16  g_tlo[(size_t)Bb*Ff*Ll];        // h^T lo [b][f][l]
__device__ float          g_part[256];                    // loss partials

// ---------------------------------------------------------------------------
// Helpers (family-safe PTX only: ldmatrix sm_75+, mma.sync bf16 sm_80+)
// ---------------------------------------------------------------------------
__device__ __forceinline__ u32 s2u(const void* p) {
    u32 a;
    asm("{ .reg .u64 t; cvta.to.shared.u64 t, %1; cvt.u32.u64 %0, t; }" : "=r"(a) : "l"(p));
    return a;
}
__device__ __forceinline__ void ldsm4(u32 a, u32& r0, u32& r1, u32& r2, u32& r3) {
    asm volatile("ldmatrix.sync.aligned.m8n8.x4.shared.b16 {%0,%1,%2,%3}, [%4];"
                 : "=r"(r0), "=r"(r1), "=r"(r2), "=r"(r3) : "r"(a));
}
__device__ __forceinline__ void ldsm2(u32 a, u32& r0, u32& r1) {
    asm volatile("ldmatrix.sync.aligned.m8n8.x2.shared.b16 {%0,%1}, [%2];"
                 : "=r"(r0), "=r"(r1) : "r"(a));
}
#define MMA(d, a0,a1,a2,a3, b0,b1)                                             \
    asm volatile("mma.sync.aligned.m16n8k16.row.col.f32.bf16.bf16.f32 "        \
        "{%0,%1,%2,%3}, {%4,%5,%6,%7}, {%8,%9}, {%0,%1,%2,%3};"                \
        : "+f"((d)[0]), "+f"((d)[1]), "+f"((d)[2]), "+f"((d)[3])               \
        : "r"(a0), "r"(a1), "r"(a2), "r"(a3), "r"(b0), "r"(b1))

__device__ __forceinline__ u32 pack_bf2(float lo, float hi) {
    u32 r; asm("cvt.rn.bf16x2.f32 %0, %1, %2;" : "=r"(r) : "f"(hi), "f"(lo)); return r;
}
__device__ __forceinline__ float bfu(unsigned short h) {
    return __bfloat162float(__ushort_as_bfloat16(h));
}

// fast exp on the FMA pipe (rel err ~2e-6 for |x| <= ~30)
__device__ __forceinline__ float fexp(float x) {
    float t = x * 1.4426950408889634f;
    float r = t + 12582912.0f;            // round-to-nearest magic (2^23 * 1.5)
    float i = r - 12582912.0f;
    float f = t - i;
    float s = __int_as_float(0x3f800000 + (__float_as_int(r) << 23));
    float p = 1.3333558146e-3f;
    p = fmaf(p, f, 9.6181291076e-3f);
    p = fmaf(p, f, 5.5504108665e-2f);
    p = fmaf(p, f, 2.4022650696e-1f);
    p = fmaf(p, f, 6.9314718056e-1f);
    p = fmaf(p, f, 1.0f);
    return p * s;
}

// ---------------------------------------------------------------------------
// K0: transpose conv_w [F,E,K] -> g_wT [(E*K), F]
// ---------------------------------------------------------------------------
__global__ void k_transpose(const float* __restrict__ w)
{
    int idx = blockIdx.x * 256 + threadIdx.x;
    if (idx < Ff*Ee*KW) {
        int f = idx / (Ee*KW);
        int r = idx - f*(Ee*KW);
        g_wT[r*Ff + f] = w[idx];
    }
}

// ---------------------------------------------------------------------------
// K1: embed + conv1d + tanh -> bf16 h (K-major) and hi/lo h^T (for GEMM2 B)
// ---------------------------------------------------------------------------
__global__ __launch_bounds__(256) void k_conv(const int* __restrict__ x,
                                              const float* __restrict__ embW,
                                              const float* __restrict__ convb)
{
    __shared__ int   toks[24];
    __shared__ float semb[24][Ee];

    int tid = threadIdx.x;
    int b   = blockIdx.y;
    int l0  = blockIdx.x * 16;

    if (tid < 24) {
        int l = l0 - 4 + tid;
        toks[tid] = (l >= 0 && l < Ll) ? x[b*Ll + l] : -1;
    }
    __syncthreads();

    for (int idx = tid; idx < 24*Ee; idx += 256) {
        int t = idx / Ee;
        int c = idx - t*Ee;
        int tok = toks[t];
        semb[t][c] = (tok >= 0) ? embW[(size_t)tok*Ee + c] : 0.f;
    }
    __syncthreads();

    int f = tid;
    float acc[16];
#pragma unroll
    for (int j = 0; j < 16; j++) acc[j] = 0.f;

    for (int e = 0; e < Ee; e++) {
        float r[24];
#pragma unroll
        for (int t = 0; t < 24; t++) r[t] = semb[t][e];
#pragma unroll
        for (int k = 0; k < KW; k++) {
            float w = g_wT[(e*KW + k)*Ff + f];
#pragma unroll
            for (int j = 0; j < 16; j++)
                acc[j] = fmaf(w, r[j + k], acc[j]);
        }
    }

    float bias = convb[f];
    __nv_bfloat16* hb  = g_hb  + ((size_t)b*Ll + l0)*Ff + f;
    __nv_bfloat16* thi = g_thi + ((size_t)b*Ff + f)*Ll + l0;
    __nv_bfloat16* tlo = g_tlo + ((size_t)b*Ff + f)*Ll + l0;
#pragma unroll
    for (int j = 0; j < 16; j++) {
        float hv = tanhf(acc[j] + bias);
        __nv_bfloat16 hh = __float2bfloat16(hv);
        __nv_bfloat16 hl = __float2bfloat16(hv - __bfloat162float(hh));
        hb[(size_t)j*Ff] = hh;
        thi[j] = hh;
        tlo[j] = hl;
    }
}

// ---------------------------------------------------------------------------
// K2: warp-MMA fused attention. Per CTA (b, 128-y tile), 32 chunks of 64 l.
//   GEMM1 (bf16 mma.sync):   s[128,64] = U[128,256] x h[64,256]^T
//   exp (poly, FMA pipe) -> e; rsum in regs; e -> bf16 hi/lo smem tiles
//   GEMM2 (3-term split):    m[128,256] += ehi*hhi + ehi*hlo + elo*hhi
//   alpha streamed unnormalized (ehi+elo), rescaled by 1/Z at the end.
// smem (bytes): U 65536 | H1 32768 | THI 32768 | TLO 32768 | EHI 16384 |
//               ELO 16384 | rsm 512  = 197120
// ---------------------------------------------------------------------------
#define SMTOT 197120

__global__ __launch_bounds__(256) void k_attn(const float* __restrict__ Uw,
                                              const float* __restrict__ fw,
                                              const float* __restrict__ fb,
                                              float* __restrict__ out)
{
    extern __shared__ char sm[];
    u32 smb = s2u(sm);
    const u32 SU   = smb;
    const u32 SH1  = smb + 65536;
    const u32 STHI = smb + 98304;
    const u32 STLO = smb + 131072;
    const u32 SEHI = smb + 163840;
    const u32 SELO = smb + 180224;
    float* rsm = (float*)(sm + 196608);   // 128 floats

    int tid  = threadIdx.x;
    int lane = tid & 31;
    int w    = tid >> 5;                   // warp 0..7
    int b    = blockIdx.y;
    int ybase = blockIdx.x * 128;

    // ---- load U tile [128 y][256 f] fp32 -> bf16, swizzled (32 16B chunks/row) ----
    for (int i = tid; i < 128*32; i += 256) {
        int yy = i >> 5, ch = i & 31;
        int gy = ybase + yy;
        float4 a0 = make_float4(0.f,0.f,0.f,0.f), a1 = a0;
        if (gy < Yy) {
            const float4* up = (const float4*)(Uw + (size_t)gy*Ff + ch*8);
            a0 = up[0]; a1 = up[1];
        }
        uint4 v;
        v.x = pack_bf2(a0.x, a0.y);
        v.y = pack_bf2(a0.z, a0.w);
        v.z = pack_bf2(a1.x, a1.y);
        v.w = pack_bf2(a1.z, a1.w);
        *(uint4*)(sm + (yy*32 + (ch ^ (yy & 7)))*16) = v;
    }

    float macc[32][4];
#pragma unroll
    for (int nt = 0; nt < 32; nt++)
#pragma unroll
        for (int j = 0; j < 4; j++) macc[nt][j] = 0.f;
    float rsum0 = 0.f, rsum1 = 0.f;

    int rowA = w*16 + (lane & 15);        // ldmatrix A row (both GEMMs)
    int aX   = lane >> 4;                 // A k-chunk selector
    int nB   = lane & 7;                  // ldmatrix B row-within-ntile
    int bX   = (lane & 15) >> 3;          // B k-chunk selector
    int r0   = w*16 + (lane >> 2);        // accumulator row (d0/d1); d2/d3 at r0+8
    int swE  = ((lane & 3) << 2);         // byte offset of this thread's e-pair in chunk

    const __nv_bfloat16* hbb = g_hb  + (size_t)b*Ll*Ff;
    const __nv_bfloat16* thb = g_thi + (size_t)b*Ff*Ll;
    const __nv_bfloat16* tlb = g_tlo + (size_t)b*Ff*Ll;
    float* alpha = out + (size_t)Bb*Yy + 1;            // misaligned base: scalar access only
    float* ablk0 = alpha + ((size_t)b*Yy + ybase)*Ll;

    for (int lc = 0; lc < 32; lc++) {
        __syncthreads();

        // ---- load GEMM1 B tile h[64 l][256 f] (swizzled) ----
        const __nv_bfloat16* hb = hbb + (size_t)lc*64*Ff;
        for (int i = tid; i < 2048; i += 256) {
            int l = i >> 5, ch = i & 31;
            uint4 v = *(const uint4*)(hb + (size_t)l*Ff + ch*8);
            *(uint4*)(sm + 65536 + (l*32 + (ch ^ (l & 7)))*16) = v;
        }
        // ---- load hT hi/lo tiles [256 f][64 l] (swizzled) ----
        for (int i = tid; i < 2048; i += 256) {
            int f = i >> 3, ch = i & 7;
            uint4 v1 = *(const uint4*)(thb + (size_t)f*Ll + lc*64 + ch*8);
            uint4 v2 = *(const uint4*)(tlb + (size_t)f*Ll + lc*64 + ch*8);
            int off = 98304 + (f*8 + (ch ^ (f & 7)))*16;
            *(uint4*)(sm + off)         = v1;
            *(uint4*)(sm + off + 32768) = v2;
        }
        __syncthreads();

        // ---- GEMM1: s[16w..+16][64] = U x h^T, K=256 (16 k-steps) ----
        float sacc[8][4];
#pragma unroll
        for (int nt = 0; nt < 8; nt++)
#pragma unroll
            for (int j = 0; j < 4; j++) sacc[nt][j] = 0.f;

#pragma unroll
        for (int ks = 0; ks < 16; ks++) {
            u32 a0, a1, a2, a3;
            ldsm4(SU + rowA*512 + (((ks*2 + aX) ^ (rowA & 7)) << 4), a0, a1, a2, a3);
#pragma unroll
            for (int nt = 0; nt < 8; nt++) {
                int n = nt*8 + nB;
                u32 b0, b1;
                ldsm2(SH1 + n*512 + (((ks*2 + bX) ^ nB) << 4), b0, b1);
                MMA(sacc[nt], a0, a1, a2, a3, b0, b1);
            }
        }

        // ---- exp (poly), rsum, e -> bf16 hi/lo tiles ----
#pragma unroll
        for (int nt = 0; nt < 8; nt++) {
            float e00 = fexp(sacc[nt][0]);
            float e01 = fexp(sacc[nt][1]);
            float e10 = fexp(sacc[nt][2]);
            float e11 = fexp(sacc[nt][3]);
            rsum0 += e00 + e01;
            rsum1 += e10 + e11;
            u32 ph0 = pack_bf2(e00, e01);
            u32 ph1 = pack_bf2(e10, e11);
            u32 pl0 = pack_bf2(e00 - bfu((unsigned short)(ph0 & 0xFFFF)),
                               e01 - bfu((unsigned short)(ph0 >> 16)));
            u32 pl1 = pack_bf2(e10 - bfu((unsigned short)(ph1 & 0xFFFF)),
                               e11 - bfu((unsigned short)(ph1 >> 16)));
            int so = ((nt ^ (r0 & 7)) << 4) + swE;     // (r0+8)&7 == r0&7
            *(u32*)(sm + 163840 + r0*128 + so)       = ph0;
            *(u32*)(sm + 163840 + (r0+8)*128 + so)   = ph1;
            *(u32*)(sm + 180224 + r0*128 + so)       = pl0;
            *(u32*)(sm + 180224 + (r0+8)*128 + so)   = pl1;
        }
        __syncthreads();

        // ---- GEMM2: m += ehi*hhi + ehi*hlo + elo*hhi (K=64, 4 k-steps) ----
#pragma unroll
        for (int ks = 0; ks < 4; ks++) {
            u32 asw = (((ks*2 + aX) ^ (rowA & 7)) << 4);
            u32 ah0, ah1, ah2, ah3, al0, al1, al2, al3;
            ldsm4(SEHI + rowA*128 + asw, ah0, ah1, ah2, ah3);
            ldsm4(SELO + rowA*128 + asw, al0, al1, al2, al3);
#pragma unroll
            for (int nt = 0; nt < 32; nt++) {
                int f = nt*8 + nB;
                u32 bsw = (((ks*2 + bX) ^ nB) << 4);
                u32 bh0, bh1, bl0, bl1;
                ldsm2(STHI + f*128 + bsw, bh0, bh1);
                ldsm2(STLO + f*128 + bsw, bl0, bl1);
                MMA(macc[nt], ah0, ah1, ah2, ah3, bh0, bh1);
                MMA(macc[nt], ah0, ah1, ah2, ah3, bl0, bl1);
                MMA(macc[nt], al0, al1, al2, al3, bh0, bh1);
            }
        }

        // ---- alpha stream: e = ehi + elo, coalesced scalar stores ----
        float* ablk = ablk0 + lc*64;
        for (int i = tid; i < 128*64; i += 256) {
            int yy = i >> 6, l = i & 63;
            if (ybase + yy < Yy) {
                int off = yy*128 + (((l >> 3) ^ (yy & 7)) << 4) + ((l & 7) << 1);
                float e = bfu(*(unsigned short*)(sm + 163840 + off))
                        + bfu(*(unsigned short*)(sm + 180224 + off));
                ablk[(size_t)yy*Ll + l] = e;
            }
        }
    }

    // ---- rowsums ----
    float v0 = rsum0 + __shfl_xor_sync(0xFFFFFFFFu, rsum0, 1);
    v0 += __shfl_xor_sync(0xFFFFFFFFu, v0, 2);
    float v1 = rsum1 + __shfl_xor_sync(0xFFFFFFFFu, rsum1, 1);
    v1 += __shfl_xor_sync(0xFFFFFFFFu, v1, 2);
    __syncthreads();
    if ((lane & 3) == 0) { rsm[r0] = v0; rsm[r0 + 8] = v1; }
    __syncthreads();

    // ---- yhat ----
    int gy0 = ybase + r0, gy1 = gy0 + 8;
    float p0 = 0.f, p1 = 0.f;
#pragma unroll
    for (int nt = 0; nt < 32; nt++) {
        int f0 = nt*8 + (lane & 3)*2;
        if (gy0 < Yy) {
            float2 w0 = *(const float2*)(fw + (size_t)gy0*Ff + f0);
            p0 = fmaf(w0.x, macc[nt][0], fmaf(w0.y, macc[nt][1], p0));
        }
        if (gy1 < Yy) {
            float2 w1 = *(const float2*)(fw + (size_t)gy1*Ff + f0);
            p1 = fmaf(w1.x, macc[nt][2], fmaf(w1.y, macc[nt][3], p1));
        }
    }
    p0 += __shfl_xor_sync(0xFFFFFFFFu, p0, 1);
    p0 += __shfl_xor_sync(0xFFFFFFFFu, p0, 2);
    p1 += __shfl_xor_sync(0xFFFFFFFFu, p1, 1);
    p1 += __shfl_xor_sync(0xFFFFFFFFu, p1, 2);
    if ((lane & 3) == 0) {
        if (gy0 < Yy) out[(size_t)b*Yy + gy0] = p0 / rsm[r0]     + fb[gy0];
        if (gy1 < Yy) out[(size_t)b*Yy + gy1] = p1 / rsm[r0 + 8] + fb[gy1];
    }
    __syncthreads();

    // ---- alpha rescale: alpha = e / Z (scalar, coalesced) ----
    for (int yy = 0; yy < 128; yy++) {
        int g = ybase + yy;
        if (g >= Yy) break;
        float inv = 1.f / rsm[yy];
        float* row = ablk0 + (size_t)yy*Ll;
        for (int l = tid; l < Ll; l += 256)
            row[l] *= inv;
    }
}

// ---------------------------------------------------------------------------
// K3: BCE loss, two-stage deterministic reduction
// ---------------------------------------------------------------------------
__global__ void k_loss1(const float* __restrict__ target, const float* __restrict__ out)
{
    __shared__ float red[256];
    int tid = threadIdx.x;
    float s = 0.f;
    for (int i = blockIdx.x*256 + tid; i < Bb*Yy; i += gridDim.x*256) {
        float yh = out[i];
        float t  = target[i];
        s += fmaxf(yh, 0.f) - yh*t + log1pf(__expf(-fabsf(yh)));
    }
    red[tid] = s;
    __syncthreads();
    for (int st = 128; st > 0; st >>= 1) {
        if (tid < st) red[tid] += red[tid + st];
        __syncthreads();
    }
    if (tid == 0) g_part[blockIdx.x] = red[0];
}

__global__ void k_loss2(float* __restrict__ out)
{
    __shared__ float red[128];
    int tid = threadIdx.x;
    red[tid] = (tid < 70) ? g_part[tid] : 0.f;
    __syncthreads();
    for (int st = 64; st > 0; st >>= 1) {
        if (tid < st) red[tid] += red[tid + st];
        __syncthreads();
    }
    if (tid == 0) out[Bb*Yy] = red[0] / (float)(Bb*Yy);
}

// ---------------------------------------------------------------------------
extern "C" void kernel_launch(void* const* d_in, const int* in_sizes, int n_in,
                              void* d_out, int out_size)
{
    const int*   x      = (const int*)d_in[0];
    const float* target = (const float*)d_in[1];
    const float* embW   = (const float*)d_in[2];
    const float* convw  = (const float*)d_in[3];
    const float* convb  = (const float*)d_in[4];
    const float* Uw     = (const float*)d_in[5];
    const float* fw     = (const float*)d_in[6];
    const float* fb     = (const float*)d_in[7];
    float* out = (float*)d_out;

    cudaFuncSetAttribute(k_attn, cudaFuncAttributeMaxDynamicSharedMemorySize, SMTOT);

    k_transpose<<<(Ff*Ee*KW + 255)/256, 256>>>(convw);
    k_conv<<<dim3(Ll/16, Bb), 256>>>(x, embW, convb);
    k_attn<<<dim3(YT, Bb), 256, SMTOT>>>(Uw, fw, fb, out);
    k_loss1<<<70, 256>>>(target, out);
    k_loss2<<<1, 128>>>(out);
}

// round 12
// speedup vs baseline: 2.8856x; 1.3452x over previous
#include <cuda_runtime.h>
#include <cuda_fp16.h>
#include <math.h>
#include <stdint.h>

// Problem constants
#define Bb    8
#define Ll    2048
#define Ee    100
#define Ff    256
#define KW    9
#define Yy    8921
#define YT    70          // ceil(8921 / 128)

typedef unsigned int u32;

// ---------------------------------------------------------------------------
// Device scratch
// ---------------------------------------------------------------------------
__device__ float  g_wT[Ee*KW*Ff];                 // conv weights [(e*K+k)][f]
__device__ __half g_hh[(size_t)Bb*Ll*Ff];         // h fp16 [b][l][f]
__device__ float  g_part[256];                    // loss partials

// ---------------------------------------------------------------------------
// Helpers (family-safe PTX only: ldmatrix sm_75+, mma.sync fp16 sm_80+)
// ---------------------------------------------------------------------------
__device__ __forceinline__ u32 s2u(const void* p) {
    u32 a;
    asm("{ .reg .u64 t; cvta.to.shared.u64 t, %1; cvt.u32.u64 %0, t; }" : "=r"(a) : "l"(p));
    return a;
}
__device__ __forceinline__ void ldsm4(u32 a, u32& r0, u32& r1, u32& r2, u32& r3) {
    asm volatile("ldmatrix.sync.aligned.m8n8.x4.shared.b16 {%0,%1,%2,%3}, [%4];"
                 : "=r"(r0), "=r"(r1), "=r"(r2), "=r"(r3) : "r"(a));
}
__device__ __forceinline__ void ldsm2(u32 a, u32& r0, u32& r1) {
    asm volatile("ldmatrix.sync.aligned.m8n8.x2.shared.b16 {%0,%1}, [%2];"
                 : "=r"(r0), "=r"(r1) : "r"(a));
}
#define MMA(d, a0,a1,a2,a3, b0,b1)                                             \
    asm volatile("mma.sync.aligned.m16n8k16.row.col.f32.f16.f16.f32 "          \
        "{%0,%1,%2,%3}, {%4,%5,%6,%7}, {%8,%9}, {%0,%1,%2,%3};"                \
        : "+f"((d)[0]), "+f"((d)[1]), "+f"((d)[2]), "+f"((d)[3])               \
        : "r"(a0), "r"(a1), "r"(a2), "r"(a3), "r"(b0), "r"(b1))

__device__ __forceinline__ u32 pack_h2(float lo, float hi) {
    __half2 h = __floats2half2_rn(lo, hi);
    return *(u32*)&h;
}

// fast exp on the FMA pipe (rel err ~2e-6 for |x| <= ~30)
__device__ __forceinline__ float fexp(float x) {
    float t = x * 1.4426950408889634f;
    float r = t + 12582912.0f;            // round-to-nearest magic (2^23 * 1.5)
    float i = r - 12582912.0f;
    float f = t - i;
    float s = __int_as_float(0x3f800000 + (__float_as_int(r) << 23));
    float p = 1.3333558146e-3f;
    p = fmaf(p, f, 9.6181291076e-3f);
    p = fmaf(p, f, 5.5504108665e-2f);
    p = fmaf(p, f, 2.4022650696e-1f);
    p = fmaf(p, f, 6.9314718056e-1f);
    p = fmaf(p, f, 1.0f);
    return p * s;
}

// ---------------------------------------------------------------------------
// K0: transpose conv_w [F,E,K] -> g_wT [(E*K), F]
// ---------------------------------------------------------------------------
__global__ void k_transpose(const float* __restrict__ w)
{
    int idx = blockIdx.x * 256 + threadIdx.x;
    if (idx < Ff*Ee*KW) {
        int f = idx / (Ee*KW);
        int r = idx - f*(Ee*KW);
        g_wT[r*Ff + f] = w[idx];
    }
}

// ---------------------------------------------------------------------------
// K1: embed + conv1d + tanh -> fp16 h (K-major)
// ---------------------------------------------------------------------------
__global__ __launch_bounds__(256) void k_conv(const int* __restrict__ x,
                                              const float* __restrict__ embW,
                                              const float* __restrict__ convb)
{
    __shared__ int   toks[24];
    __shared__ float semb[24][Ee];

    int tid = threadIdx.x;
    int b   = blockIdx.y;
    int l0  = blockIdx.x * 16;

    if (tid < 24) {
        int l = l0 - 4 + tid;
        toks[tid] = (l >= 0 && l < Ll) ? x[b*Ll + l] : -1;
    }
    __syncthreads();

    for (int idx = tid; idx < 24*Ee; idx += 256) {
        int t = idx / Ee;
        int c = idx - t*Ee;
        int tok = toks[t];
        semb[t][c] = (tok >= 0) ? embW[(size_t)tok*Ee + c] : 0.f;
    }
    __syncthreads();

    int f = tid;
    float acc[16];
#pragma unroll
    for (int j = 0; j < 16; j++) acc[j] = 0.f;

    for (int e = 0; e < Ee; e++) {
        float r[24];
#pragma unroll
        for (int t = 0; t < 24; t++) r[t] = semb[t][e];
#pragma unroll
        for (int k = 0; k < KW; k++) {
            float w = g_wT[(e*KW + k)*Ff + f];
#pragma unroll
            for (int j = 0; j < 16; j++)
                acc[j] = fmaf(w, r[j + k], acc[j]);
        }
    }

    float bias = convb[f];
    __half* hh = g_hh + ((size_t)b*Ll + l0)*Ff + f;
#pragma unroll
    for (int j = 0; j < 16; j++)
        hh[(size_t)j*Ff] = __float2half_rn(tanhf(acc[j] + bias));
}

// ---------------------------------------------------------------------------
// K2: warp-MMA fused attention (fp16 MMA path), GEMM2 eliminated:
//   yhat_y = sum_l e_yl * c_yl / Z,  c = FW x h^T (scores-shaped GEMM).
//   Per CTA (b, 128-y tile), 32 chunks of 64 l:
//     s[128,64] = U x h^T ;  c[128,64] = FW x h^T   (B tile ldsm shared)
//     e = fexp(s); rsum += e; ydot += e*c; stage e -> coalesced alpha stream
//   Then yhat = ydot/Z + fb; alpha rescaled by 1/Z in-place.
// smem: U 64K | FW 64K | H 32K | e-stage 32K | rsm 512  = 197120 B
// ---------------------------------------------------------------------------
#define SMTOT 197120

__global__ __launch_bounds__(256) void k_attn(const float* __restrict__ Uw,
                                              const float* __restrict__ fw,
                                              const float* __restrict__ fb,
                                              float* __restrict__ out)
{
    extern __shared__ char sm[];
    u32 smb  = s2u(sm);
    const u32 SU  = smb;
    const u32 SFW = smb + 65536;
    const u32 SH  = smb + 131072;
    float* esm = (float*)(sm + 163840);   // e stage [64 l][128 y] xor layout
    float* rsm = (float*)(sm + 196608);   // 128 floats

    int tid  = threadIdx.x;
    int lane = tid & 31;
    int w    = tid >> 5;                   // warp 0..7
    int b    = blockIdx.y;
    int ybase = blockIdx.x * 128;

    // ---- load U and FW tiles [128 y][256 f] fp32 -> fp16, swizzled ----
    for (int i = tid; i < 128*32; i += 256) {
        int yy = i >> 5, ch = i & 31;
        int gy = ybase + yy;
        float4 u0 = make_float4(0.f,0.f,0.f,0.f), u1 = u0, f0 = u0, f1 = u0;
        if (gy < Yy) {
            const float4* up = (const float4*)(Uw + (size_t)gy*Ff + ch*8);
            const float4* fp = (const float4*)(fw + (size_t)gy*Ff + ch*8);
            u0 = up[0]; u1 = up[1];
            f0 = fp[0]; f1 = fp[1];
        }
        int off = (yy*32 + (ch ^ (yy & 7)))*16;
        uint4 v;
        v.x = pack_h2(u0.x, u0.y);  v.y = pack_h2(u0.z, u0.w);
        v.z = pack_h2(u1.x, u1.y);  v.w = pack_h2(u1.z, u1.w);
        *(uint4*)(sm + off) = v;
        v.x = pack_h2(f0.x, f0.y);  v.y = pack_h2(f0.z, f0.w);
        v.z = pack_h2(f1.x, f1.y);  v.w = pack_h2(f1.z, f1.w);
        *(uint4*)(sm + 65536 + off) = v;
    }

    int rowA = w*16 + (lane & 15);        // ldmatrix A row
    int aX   = lane >> 4;                 // A k-chunk selector
    int nB   = lane & 7;                  // ldmatrix B row-within-ntile
    int bX   = (lane & 15) >> 3;          // B k-chunk selector
    int r0   = w*16 + (lane >> 2);        // accumulator rows r0, r0+8

    float rsum0 = 0.f, rsum1 = 0.f;
    float ydot0 = 0.f, ydot1 = 0.f;

    const __half* hbb = g_hh + (size_t)b*Ll*Ff;
    float* alpha = out + (size_t)Bb*Yy + 1;            // misaligned base: scalar access only
    float* ablk0 = alpha + ((size_t)b*Yy + ybase)*Ll;

    for (int lc = 0; lc < 32; lc++) {
        __syncthreads();   // protects SH + e-stage reuse

        // ---- load h tile [64 l][256 f] (swizzled) ----
        const __half* hb = hbb + (size_t)lc*64*Ff;
        for (int i = tid; i < 2048; i += 256) {
            int l = i >> 5, ch = i & 31;
            uint4 v = *(const uint4*)(hb + (size_t)l*Ff + ch*8);
            *(uint4*)(sm + 131072 + (l*32 + (ch ^ (l & 7)))*16) = v;
        }
        __syncthreads();

        // ---- dual GEMM: s = U x h^T,  c = FW x h^T  (shared B ldsm) ----
        float sacc[8][4], cacc[8][4];
#pragma unroll
        for (int nt = 0; nt < 8; nt++)
#pragma unroll
            for (int j = 0; j < 4; j++) { sacc[nt][j] = 0.f; cacc[nt][j] = 0.f; }

#pragma unroll
        for (int ks = 0; ks < 16; ks++) {
            u32 asw = (((ks*2 + aX) ^ (rowA & 7)) << 4);
            u32 a0, a1, a2, a3, q0, q1, q2, q3;
            ldsm4(SU  + rowA*512 + asw, a0, a1, a2, a3);
            ldsm4(SFW + rowA*512 + asw, q0, q1, q2, q3);
#pragma unroll
            for (int nt = 0; nt < 8; nt++) {
                int n = nt*8 + nB;
                u32 b0, b1;
                ldsm2(SH + n*512 + (((ks*2 + bX) ^ nB) << 4), b0, b1);
                MMA(sacc[nt], a0, a1, a2, a3, b0, b1);
                MMA(cacc[nt], q0, q1, q2, q3, b0, b1);
            }
        }

        // ---- e = exp(s); rsum; ydot += e*c; stage e ----
#pragma unroll
        for (int nt = 0; nt < 8; nt++) {
            float e00 = fexp(sacc[nt][0]);
            float e01 = fexp(sacc[nt][1]);
            float e10 = fexp(sacc[nt][2]);
            float e11 = fexp(sacc[nt][3]);
            rsum0 += e00 + e01;
            rsum1 += e10 + e11;
            ydot0 = fmaf(e00, cacc[nt][0], fmaf(e01, cacc[nt][1], ydot0));
            ydot1 = fmaf(e10, cacc[nt][2], fmaf(e11, cacc[nt][3], ydot1));
            int l = nt*8 + (lane & 3)*2;
            esm[(l  )*128 + ((r0   + l    ) & 127)] = e00;
            esm[(l+1)*128 + ((r0   + l + 1) & 127)] = e01;
            esm[(l  )*128 + ((r0+8 + l    ) & 127)] = e10;
            esm[(l+1)*128 + ((r0+8 + l + 1) & 127)] = e11;
        }
        __syncthreads();

        // ---- coalesced scalar alpha stream (unnormalized e) ----
        float* ablk = ablk0 + lc*64;
        for (int i = tid; i < 128*64; i += 256) {
            int yy = i >> 6, l = i & 63;
            if (ybase + yy < Yy)
                ablk[(size_t)yy*Ll + l] = esm[l*128 + ((yy + l) & 127)];
        }
    }

    // ---- reduce rowsums and ydot across the lane quad ----
    rsum0 += __shfl_xor_sync(0xFFFFFFFFu, rsum0, 1);
    rsum0 += __shfl_xor_sync(0xFFFFFFFFu, rsum0, 2);
    rsum1 += __shfl_xor_sync(0xFFFFFFFFu, rsum1, 1);
    rsum1 += __shfl_xor_sync(0xFFFFFFFFu, rsum1, 2);
    ydot0 += __shfl_xor_sync(0xFFFFFFFFu, ydot0, 1);
    ydot0 += __shfl_xor_sync(0xFFFFFFFFu, ydot0, 2);
    ydot1 += __shfl_xor_sync(0xFFFFFFFFu, ydot1, 1);
    ydot1 += __shfl_xor_sync(0xFFFFFFFFu, ydot1, 2);
    __syncthreads();
    if ((lane & 3) == 0) { rsm[r0] = rsum0; rsm[r0 + 8] = rsum1; }

    // ---- yhat ----
    if ((lane & 3) == 0) {
        int gy0 = ybase + r0, gy1 = gy0 + 8;
        if (gy0 < Yy) out[(size_t)b*Yy + gy0] = ydot0 / rsum0 + fb[gy0];
        if (gy1 < Yy) out[(size_t)b*Yy + gy1] = ydot1 / rsum1 + fb[gy1];
    }
    __syncthreads();

    // ---- alpha rescale: alpha = e / Z (scalar, coalesced) ----
    for (int yy = 0; yy < 128; yy++) {
        int g = ybase + yy;
        if (g >= Yy) break;
        float inv = 1.f / rsm[yy];
        float* row = ablk0 + (size_t)yy*Ll;
        for (int l = tid; l < Ll; l += 256)
            row[l] *= inv;
    }
}

// ---------------------------------------------------------------------------
// K3: BCE loss, two-stage deterministic reduction
// ---------------------------------------------------------------------------
__global__ void k_loss1(const float* __restrict__ target, const float* __restrict__ out)
{
    __shared__ float red[256];
    int tid = threadIdx.x;
    float s = 0.f;
    for (int i = blockIdx.x*256 + tid; i < Bb*Yy; i += gridDim.x*256) {
        float yh = out[i];
        float t  = target[i];
        s += fmaxf(yh, 0.f) - yh*t + log1pf(__expf(-fabsf(yh)));
    }
    red[tid] = s;
    __syncthreads();
    for (int st = 128; st > 0; st >>= 1) {
        if (tid < st) red[tid] += red[tid + st];
        __syncthreads();
    }
    if (tid == 0) g_part[blockIdx.x] = red[0];
}

__global__ void k_loss2(float* __restrict__ out)
{
    __shared__ float red[128];
    int tid = threadIdx.x;
    red[tid] = (tid < 70) ? g_part[tid] : 0.f;
    __syncthreads();
    for (int st = 64; st > 0; st >>= 1) {
        if (tid < st) red[tid] += red[tid + st];
        __syncthreads();
    }
    if (tid == 0) out[Bb*Yy] = red[0] / (float)(Bb*Yy);
}

// ---------------------------------------------------------------------------
extern "C" void kernel_launch(void* const* d_in, const int* in_sizes, int n_in,
                              void* d_out, int out_size)
{
    const int*   x      = (const int*)d_in[0];
    const float* target = (const float*)d_in[1];
    const float* embW   = (const float*)d_in[2];
    const float* convw  = (const float*)d_in[3];
    const float* convb  = (const float*)d_in[4];
    const float* Uw     = (const float*)d_in[5];
    const float* fw     = (const float*)d_in[6];
    const float* fb     = (const float*)d_in[7];
    float* out = (float*)d_out;

    cudaFuncSetAttribute(k_attn, cudaFuncAttributeMaxDynamicSharedMemorySize, SMTOT);

    k_transpose<<<(Ff*Ee*KW + 255)/256, 256>>>(convw);
    k_conv<<<dim3(Ll/16, Bb), 256>>>(x, embW, convb);
    k_attn<<<dim3(YT, Bb), 256, SMTOT>>>(Uw, fw, fb, out);
    k_loss1<<<70, 256>>>(target, out);
    k_loss2<<<1, 128>>>(out);
}

// round 13
// speedup vs baseline: 3.1341x; 1.0861x over previous
#include <cuda_runtime.h>
#include <cuda_fp16.h>
#include <math.h>
#include <stdint.h>

// Problem constants
#define Bb    8
#define Ll    2048
#define Ee    100
#define Ff    256
#define KW    9
#define Yy    8921
#define YT    70          // ceil(8921 / 128)

typedef unsigned int u32;

// ---------------------------------------------------------------------------
// Device scratch
// ---------------------------------------------------------------------------
__device__ float  g_wT[Ee*KW*Ff];                 // conv weights [(e*K+k)][f]
__device__ __half g_hh[(size_t)Bb*Ll*Ff];         // h fp16 [b][l][f]
__device__ float  g_part[256];                    // loss partials

// ---------------------------------------------------------------------------
// Helpers (family-safe PTX only: ldmatrix sm_75+, mma.sync fp16 sm_80+,
//          cp.async sm_80+)
// ---------------------------------------------------------------------------
__device__ __forceinline__ u32 s2u(const void* p) {
    u32 a;
    asm("{ .reg .u64 t; cvta.to.shared.u64 t, %1; cvt.u32.u64 %0, t; }" : "=r"(a) : "l"(p));
    return a;
}
__device__ __forceinline__ void ldsm4(u32 a, u32& r0, u32& r1, u32& r2, u32& r3) {
    asm volatile("ldmatrix.sync.aligned.m8n8.x4.shared.b16 {%0,%1,%2,%3}, [%4];"
                 : "=r"(r0), "=r"(r1), "=r"(r2), "=r"(r3) : "r"(a));
}
#define MMA(d, a0,a1,a2,a3, b0,b1)                                             \
    asm volatile("mma.sync.aligned.m16n8k16.row.col.f32.f16.f16.f32 "          \
        "{%0,%1,%2,%3}, {%4,%5,%6,%7}, {%8,%9}, {%0,%1,%2,%3};"                \
        : "+f"((d)[0]), "+f"((d)[1]), "+f"((d)[2]), "+f"((d)[3])               \
        : "r"(a0), "r"(a1), "r"(a2), "r"(a3), "r"(b0), "r"(b1))

#define CP_ASYNC16(dst, src)                                                   \
    asm volatile("cp.async.cg.shared.global [%0], [%1], 16;"                   \
                 :: "r"(dst), "l"(src) : "memory")
#define CP_COMMIT()  asm volatile("cp.async.commit_group;" ::: "memory")
#define CP_WAIT0()   asm volatile("cp.async.wait_group 0;" ::: "memory")

__device__ __forceinline__ u32 pack_h2(float lo, float hi) {
    __half2 h = __floats2half2_rn(lo, hi);
    return *(u32*)&h;
}

// fast exp on the FMA pipe (rel err ~2e-6 for |x| <= ~30)
__device__ __forceinline__ float fexp(float x) {
    float t = x * 1.4426950408889634f;
    float r = t + 12582912.0f;            // round-to-nearest magic (2^23 * 1.5)
    float i = r - 12582912.0f;
    float f = t - i;
    float s = __int_as_float(0x3f800000 + (__float_as_int(r) << 23));
    float p = 1.3333558146e-3f;
    p = fmaf(p, f, 9.6181291076e-3f);
    p = fmaf(p, f, 5.5504108665e-2f);
    p = fmaf(p, f, 2.4022650696e-1f);
    p = fmaf(p, f, 6.9314718056e-1f);
    p = fmaf(p, f, 1.0f);
    return p * s;
}

// ---------------------------------------------------------------------------
// K0: transpose conv_w [F,E,K] -> g_wT [(E*K), F]
// ---------------------------------------------------------------------------
__global__ void k_transpose(const float* __restrict__ w)
{
    int idx = blockIdx.x * 256 + threadIdx.x;
    if (idx < Ff*Ee*KW) {
        int f = idx / (Ee*KW);
        int r = idx - f*(Ee*KW);
        g_wT[r*Ff + f] = w[idx];
    }
}

// ---------------------------------------------------------------------------
// K1: embed + conv1d + tanh -> fp16 h (K-major)
// ---------------------------------------------------------------------------
__global__ __launch_bounds__(256) void k_conv(const int* __restrict__ x,
                                              const float* __restrict__ embW,
                                              const float* __restrict__ convb)
{
    __shared__ int   toks[24];
    __shared__ float semb[24][Ee];

    int tid = threadIdx.x;
    int b   = blockIdx.y;
    int l0  = blockIdx.x * 16;

    if (tid < 24) {
        int l = l0 - 4 + tid;
        toks[tid] = (l >= 0 && l < Ll) ? x[b*Ll + l] : -1;
    }
    __syncthreads();

    for (int idx = tid; idx < 24*Ee; idx += 256) {
        int t = idx / Ee;
        int c = idx - t*Ee;
        int tok = toks[t];
        semb[t][c] = (tok >= 0) ? embW[(size_t)tok*Ee + c] : 0.f;
    }
    __syncthreads();

    int f = tid;
    float acc[16];
#pragma unroll
    for (int j = 0; j < 16; j++) acc[j] = 0.f;

    for (int e = 0; e < Ee; e++) {
        float r[24];
#pragma unroll
        for (int t = 0; t < 24; t++) r[t] = semb[t][e];
#pragma unroll
        for (int k = 0; k < KW; k++) {
            float w = g_wT[(e*KW + k)*Ff + f];
#pragma unroll
            for (int j = 0; j < 16; j++)
                acc[j] = fmaf(w, r[j + k], acc[j]);
        }
    }

    float bias = convb[f];
    __half* hh = g_hh + ((size_t)b*Ll + l0)*Ff + f;
#pragma unroll
    for (int j = 0; j < 16; j++)
        hh[(size_t)j*Ff] = __float2half_rn(tanhf(acc[j] + bias));
}

// ---------------------------------------------------------------------------
// K2: warp-MMA fused attention (fp16), GEMM2 eliminated via summation swap,
//     cp.async double-buffered h tiles, B operands via 2-ntile ldmatrix.x4.
//   yhat_y = sum_l e_yl * c_yl / Z,  c = FW x h^T.
// smem: U 64K | FW 64K | H0 32K | H1 32K | e-stage 32K | rsm 512 = 229888 B
// ---------------------------------------------------------------------------
#define SMTOT 229888

__global__ __launch_bounds__(256) void k_attn(const float* __restrict__ Uw,
                                              const float* __restrict__ fw,
                                              const float* __restrict__ fb,
                                              float* __restrict__ out)
{
    extern __shared__ char sm[];
    u32 smb  = s2u(sm);
    const u32 SU  = smb;
    const u32 SFW = smb + 65536;
    const u32 SH0 = smb + 131072;         // two 32 KB h buffers
    float* esm = (float*)(sm + 196608);   // e stage [64 l][128 y] xor layout
    float* rsm = (float*)(sm + 229376);   // 128 floats

    int tid  = threadIdx.x;
    int lane = tid & 31;
    int w    = tid >> 5;                   // warp 0..7
    int b    = blockIdx.y;
    int ybase = blockIdx.x * 128;

    const __half* hbb = g_hh + (size_t)b*Ll*Ff;

    // ---- prefetch h chunk 0 into buffer 0 (overlaps U/FW conversion) ----
    {
        const __half* hb = hbb;
        for (int i = tid; i < 2048; i += 256) {
            int l = i >> 5, ch = i & 31;
            CP_ASYNC16(SH0 + (l*32 + (ch ^ (l & 7)))*16, hb + (size_t)l*Ff + ch*8);
        }
        CP_COMMIT();
    }

    // ---- load U and FW tiles [128 y][256 f] fp32 -> fp16, swizzled ----
    for (int i = tid; i < 128*32; i += 256) {
        int yy = i >> 5, ch = i & 31;
        int gy = ybase + yy;
        float4 u0 = make_float4(0.f,0.f,0.f,0.f), u1 = u0, f0 = u0, f1 = u0;
        if (gy < Yy) {
            const float4* up = (const float4*)(Uw + (size_t)gy*Ff + ch*8);
            const float4* fp = (const float4*)(fw + (size_t)gy*Ff + ch*8);
            u0 = up[0]; u1 = up[1];
            f0 = fp[0]; f1 = fp[1];
        }
        int off = (yy*32 + (ch ^ (yy & 7)))*16;
        uint4 v;
        v.x = pack_h2(u0.x, u0.y);  v.y = pack_h2(u0.z, u0.w);
        v.z = pack_h2(u1.x, u1.y);  v.w = pack_h2(u1.z, u1.w);
        *(uint4*)(sm + off) = v;
        v.x = pack_h2(f0.x, f0.y);  v.y = pack_h2(f0.z, f0.w);
        v.z = pack_h2(f1.x, f1.y);  v.w = pack_h2(f1.z, f1.w);
        *(uint4*)(sm + 65536 + off) = v;
    }

    int rowA = w*16 + (lane & 15);        // ldmatrix A row
    int aX   = lane >> 4;                 // A k-chunk selector
    int nb8  = lane & 7;                  // B ldmatrix row-within-8
    int nHi  = lane >> 4;                 // B: which of the 2 n-tiles this lane addresses
    int bX   = (lane >> 3) & 1;           // B k-chunk selector
    int r0   = w*16 + (lane >> 2);        // accumulator rows r0, r0+8

    float rsum0 = 0.f, rsum1 = 0.f;
    float ydot0 = 0.f, ydot1 = 0.f;

    float* alpha = out + (size_t)Bb*Yy + 1;            // misaligned base: scalar access only
    float* ablk0 = alpha + ((size_t)b*Yy + ybase)*Ll;

    for (int lc = 0; lc < 32; lc++) {
        CP_WAIT0();
        __syncthreads();   // h[lc] visible to all; buffer (lc+1)&1 fully consumed

        // ---- issue next chunk's h load into the alternate buffer ----
        if (lc + 1 < 32) {
            const __half* hb = hbb + (size_t)(lc + 1)*64*Ff;
            u32 dst = SH0 + ((lc + 1) & 1)*32768;
            for (int i = tid; i < 2048; i += 256) {
                int l = i >> 5, ch = i & 31;
                CP_ASYNC16(dst + (l*32 + (ch ^ (l & 7)))*16, hb + (size_t)l*Ff + ch*8);
            }
            CP_COMMIT();
        }

        const u32 SH = SH0 + (lc & 1)*32768;

        // ---- dual GEMM: s = U x h^T,  c = FW x h^T (B ldsm.x4, 2 n-tiles) ----
        float sacc[8][4], cacc[8][4];
#pragma unroll
        for (int nt = 0; nt < 8; nt++)
#pragma unroll
            for (int j = 0; j < 4; j++) { sacc[nt][j] = 0.f; cacc[nt][j] = 0.f; }

#pragma unroll
        for (int ks = 0; ks < 16; ks++) {
            u32 asw = (((ks*2 + aX) ^ (rowA & 7)) << 4);
            u32 a0, a1, a2, a3, q0, q1, q2, q3;
            ldsm4(SU  + rowA*512 + asw, a0, a1, a2, a3);
            ldsm4(SFW + rowA*512 + asw, q0, q1, q2, q3);
#pragma unroll
            for (int ntp = 0; ntp < 4; ntp++) {
                int n = (ntp*2 + nHi)*8 + nb8;
                u32 b0, b1, b2, b3;
                ldsm4(SH + n*512 + (((ks*2 + bX) ^ (n & 7)) << 4), b0, b1, b2, b3);
                MMA(sacc[ntp*2],     a0, a1, a2, a3, b0, b1);
                MMA(cacc[ntp*2],     q0, q1, q2, q3, b0, b1);
                MMA(sacc[ntp*2 + 1], a0, a1, a2, a3, b2, b3);
                MMA(cacc[ntp*2 + 1], q0, q1, q2, q3, b2, b3);
            }
        }

        // ---- e = exp(s); rsum; ydot += e*c; stage e ----
#pragma unroll
        for (int nt = 0; nt < 8; nt++) {
            float e00 = fexp(sacc[nt][0]);
            float e01 = fexp(sacc[nt][1]);
            float e10 = fexp(sacc[nt][2]);
            float e11 = fexp(sacc[nt][3]);
            rsum0 += e00 + e01;
            rsum1 += e10 + e11;
            ydot0 = fmaf(e00, cacc[nt][0], fmaf(e01, cacc[nt][1], ydot0));
            ydot1 = fmaf(e10, cacc[nt][2], fmaf(e11, cacc[nt][3], ydot1));
            int l = nt*8 + (lane & 3)*2;
            esm[(l  )*128 + ((r0   + l    ) & 127)] = e00;
            esm[(l+1)*128 + ((r0   + l + 1) & 127)] = e01;
            esm[(l  )*128 + ((r0+8 + l    ) & 127)] = e10;
            esm[(l+1)*128 + ((r0+8 + l + 1) & 127)] = e11;
        }
        __syncthreads();

        // ---- coalesced scalar alpha stream (unnormalized e) ----
        float* ablk = ablk0 + lc*64;
        for (int i = tid; i < 128*64; i += 256) {
            int yy = i >> 6, l = i & 63;
            if (ybase + yy < Yy)
                ablk[(size_t)yy*Ll + l] = esm[l*128 + ((yy + l) & 127)];
        }
    }

    // ---- reduce rowsums and ydot across the lane quad ----
    rsum0 += __shfl_xor_sync(0xFFFFFFFFu, rsum0, 1);
    rsum0 += __shfl_xor_sync(0xFFFFFFFFu, rsum0, 2);
    rsum1 += __shfl_xor_sync(0xFFFFFFFFu, rsum1, 1);
    rsum1 += __shfl_xor_sync(0xFFFFFFFFu, rsum1, 2);
    ydot0 += __shfl_xor_sync(0xFFFFFFFFu, ydot0, 1);
    ydot0 += __shfl_xor_sync(0xFFFFFFFFu, ydot0, 2);
    ydot1 += __shfl_xor_sync(0xFFFFFFFFu, ydot1, 1);
    ydot1 += __shfl_xor_sync(0xFFFFFFFFu, ydot1, 2);
    __syncthreads();
    if ((lane & 3) == 0) { rsm[r0] = rsum0; rsm[r0 + 8] = rsum1; }

    // ---- yhat ----
    if ((lane & 3) == 0) {
        int gy0 = ybase + r0, gy1 = gy0 + 8;
        if (gy0 < Yy) out[(size_t)b*Yy + gy0] = ydot0 / rsum0 + fb[gy0];
        if (gy1 < Yy) out[(size_t)b*Yy + gy1] = ydot1 / rsum1 + fb[gy1];
    }
    __syncthreads();

    // ---- alpha rescale: alpha = e / Z (scalar, coalesced) ----
    for (int yy = 0; yy < 128; yy++) {
        int g = ybase + yy;
        if (g >= Yy) break;
        float inv = 1.f / rsm[yy];
        float* row = ablk0 + (size_t)yy*Ll;
        for (int l = tid; l < Ll; l += 256)
            row[l] *= inv;
    }
}

// ---------------------------------------------------------------------------
// K3: BCE loss, two-stage deterministic reduction
// ---------------------------------------------------------------------------
__global__ void k_loss1(const float* __restrict__ target, const float* __restrict__ out)
{
    __shared__ float red[256];
    int tid = threadIdx.x;
    float s = 0.f;
    for (int i = blockIdx.x*256 + tid; i < Bb*Yy; i += gridDim.x*256) {
        float yh = out[i];
        float t  = target[i];
        s += fmaxf(yh, 0.f) - yh*t + log1pf(__expf(-fabsf(yh)));
    }
    red[tid] = s;
    __syncthreads();
    for (int st = 128; st > 0; st >>= 1) {
        if (tid < st) red[tid] += red[tid + st];
        __syncthreads();
    }
    if (tid == 0) g_part[blockIdx.x] = red[0];
}

__global__ void k_loss2(float* __restrict__ out)
{
    __shared__ float red[128];
    int tid = threadIdx.x;
    red[tid] = (tid < 70) ? g_part[tid] : 0.f;
    __syncthreads();
    for (int st = 64; st > 0; st >>= 1) {
        if (tid < st) red[tid] += red[tid + st];
        __syncthreads();
    }
    if (tid == 0) out[Bb*Yy] = red[0] / (float)(Bb*Yy);
}

// ---------------------------------------------------------------------------
extern "C" void kernel_launch(void* const* d_in, const int* in_sizes, int n_in,
                              void* d_out, int out_size)
{
    const int*   x      = (const int*)d_in[0];
    const float* target = (const float*)d_in[1];
    const float* embW   = (const float*)d_in[2];
    const float* convw  = (const float*)d_in[3];
    const float* convb  = (const float*)d_in[4];
    const float* Uw     = (const float*)d_in[5];
    const float* fw     = (const float*)d_in[6];
    const float* fb     = (const float*)d_in[7];
    float* out = (float*)d_out;

    cudaFuncSetAttribute(k_attn, cudaFuncAttributeMaxDynamicSharedMemorySize, SMTOT);

    k_transpose<<<(Ff*Ee*KW + 255)/256, 256>>>(convw);
    k_conv<<<dim3(Ll/16, Bb), 256>>>(x, embW, convb);
    k_attn<<<dim3(YT, Bb), 256, SMTOT>>>(Uw, fw, fb, out);
    k_loss1<<<70, 256>>>(target, out);
    k_loss2<<<1, 128>>>(out);
}

// round 14
// speedup vs baseline: 3.8546x; 1.2299x over previous
#include <cuda_runtime.h>
#include <cuda_fp16.h>
#include <math.h>
#include <stdint.h>

// Problem constants
#define Bb    8
#define Ll    2048
#define Ee    100
#define Ff    256
#define KW    9
#define Yy    8921
#define YT    140         // ceil(8921 / 64)

typedef unsigned int u32;

// ---------------------------------------------------------------------------
// Device scratch
// ---------------------------------------------------------------------------
__device__ float  g_wT[Ee*KW*Ff];                 // conv weights [(e*K+k)][f]
__device__ __half g_hh[(size_t)Bb*Ll*Ff];         // h fp16 [b][l][f]
__device__ float  g_part[256];                    // loss partials

// ---------------------------------------------------------------------------
// Helpers (family-safe PTX only: ldmatrix sm_75+, mma.sync fp16 sm_80+,
//          cp.async sm_80+)
// ---------------------------------------------------------------------------
__device__ __forceinline__ u32 s2u(const void* p) {
    u32 a;
    asm("{ .reg .u64 t; cvta.to.shared.u64 t, %1; cvt.u32.u64 %0, t; }" : "=r"(a) : "l"(p));
    return a;
}
__device__ __forceinline__ void ldsm4(u32 a, u32& r0, u32& r1, u32& r2, u32& r3) {
    asm volatile("ldmatrix.sync.aligned.m8n8.x4.shared.b16 {%0,%1,%2,%3}, [%4];"
                 : "=r"(r0), "=r"(r1), "=r"(r2), "=r"(r3) : "r"(a));
}
#define MMA(d, a0,a1,a2,a3, b0,b1)                                             \
    asm volatile("mma.sync.aligned.m16n8k16.row.col.f32.f16.f16.f32 "          \
        "{%0,%1,%2,%3}, {%4,%5,%6,%7}, {%8,%9}, {%0,%1,%2,%3};"                \
        : "+f"((d)[0]), "+f"((d)[1]), "+f"((d)[2]), "+f"((d)[3])               \
        : "r"(a0), "r"(a1), "r"(a2), "r"(a3), "r"(b0), "r"(b1))

#define CP_ASYNC16(dst, src)                                                   \
    asm volatile("cp.async.cg.shared.global [%0], [%1], 16;"                   \
                 :: "r"(dst), "l"(src) : "memory")
#define CP_COMMIT()  asm volatile("cp.async.commit_group;" ::: "memory")
#define CP_WAIT0()   asm volatile("cp.async.wait_group 0;" ::: "memory")

__device__ __forceinline__ u32 pack_h2(float lo, float hi) {
    __half2 h = __floats2half2_rn(lo, hi);
    return *(u32*)&h;
}

// fast exp on the FMA pipe (rel err ~2e-6 for |x| <= ~30)
__device__ __forceinline__ float fexp(float x) {
    float t = x * 1.4426950408889634f;
    float r = t + 12582912.0f;            // round-to-nearest magic (2^23 * 1.5)
    float i = r - 12582912.0f;
    float f = t - i;
    float s = __int_as_float(0x3f800000 + (__float_as_int(r) << 23));
    float p = 1.3333558146e-3f;
    p = fmaf(p, f, 9.6181291076e-3f);
    p = fmaf(p, f, 5.5504108665e-2f);
    p = fmaf(p, f, 2.4022650696e-1f);
    p = fmaf(p, f, 6.9314718056e-1f);
    p = fmaf(p, f, 1.0f);
    return p * s;
}

// ---------------------------------------------------------------------------
// K0: transpose conv_w [F,E,K] -> g_wT [(E*K), F]
// ---------------------------------------------------------------------------
__global__ void k_transpose(const float* __restrict__ w)
{
    int idx = blockIdx.x * 256 + threadIdx.x;
    if (idx < Ff*Ee*KW) {
        int f = idx / (Ee*KW);
        int r = idx - f*(Ee*KW);
        g_wT[r*Ff + f] = w[idx];
    }
}

// ---------------------------------------------------------------------------
// K1: embed + conv1d + tanh -> fp16 h (K-major)
// ---------------------------------------------------------------------------
__global__ __launch_bounds__(256) void k_conv(const int* __restrict__ x,
                                              const float* __restrict__ embW,
                                              const float* __restrict__ convb)
{
    __shared__ int   toks[24];
    __shared__ float semb[24][Ee];

    int tid = threadIdx.x;
    int b   = blockIdx.y;
    int l0  = blockIdx.x * 16;

    if (tid < 24) {
        int l = l0 - 4 + tid;
        toks[tid] = (l >= 0 && l < Ll) ? x[b*Ll + l] : -1;
    }
    __syncthreads();

    for (int idx = tid; idx < 24*Ee; idx += 256) {
        int t = idx / Ee;
        int c = idx - t*Ee;
        int tok = toks[t];
        semb[t][c] = (tok >= 0) ? embW[(size_t)tok*Ee + c] : 0.f;
    }
    __syncthreads();

    int f = tid;
    float acc[16];
#pragma unroll
    for (int j = 0; j < 16; j++) acc[j] = 0.f;

    for (int e = 0; e < Ee; e++) {
        float r[24];
#pragma unroll
        for (int t = 0; t < 24; t++) r[t] = semb[t][e];
#pragma unroll
        for (int k = 0; k < KW; k++) {
            float w = g_wT[(e*KW + k)*Ff + f];
#pragma unroll
            for (int j = 0; j < 16; j++)
                acc[j] = fmaf(w, r[j + k], acc[j]);
        }
    }

    float bias = convb[f];
    __half* hh = g_hh + ((size_t)b*Ll + l0)*Ff + f;
#pragma unroll
    for (int j = 0; j < 16; j++)
        hh[(size_t)j*Ff] = __float2half_rn(tanhf(acc[j] + bias));
}

// ---------------------------------------------------------------------------
// K2: warp-MMA fused attention (fp16), 2-CTA/SM co-residency layout:
//   64-y tile per CTA, 128 threads (4 warps x 16 rows), 32-l chunks,
//   cp.async double-buffered h, dual GEMM (s = U x h^T, c = FW x h^T),
//   yhat via summation swap, unnormalized-e alpha stream + 1/Z rescale.
// smem/CTA: U 32K | FW 32K | H 2x16K | e-stage 8K | rsm 256B = 106752 B
// ---------------------------------------------------------------------------
#define SMTOT 106752

__global__ __launch_bounds__(128, 2) void k_attn(const float* __restrict__ Uw,
                                                 const float* __restrict__ fw,
                                                 const float* __restrict__ fb,
                                                 float* __restrict__ out)
{
    extern __shared__ char sm[];
    u32 smb  = s2u(sm);
    const u32 SU  = smb;
    const u32 SFW = smb + 32768;
    const u32 SH0 = smb + 65536;          // two 16 KB h buffers
    float* esm = (float*)(sm + 98304);    // e stage [32 l][64 y] xor layout
    float* rsm = (float*)(sm + 106496);   // 64 floats

    int tid  = threadIdx.x;
    int lane = tid & 31;
    int w    = tid >> 5;                   // warp 0..3
    int b    = blockIdx.y;
    int ybase = blockIdx.x * 64;

    const __half* hbb = g_hh + (size_t)b*Ll*Ff;

    // ---- prefetch h chunk 0 into buffer 0 (overlaps U/FW conversion) ----
    {
        const __half* hb = hbb;
        for (int i = tid; i < 1024; i += 128) {
            int l = i >> 5, ch = i & 31;
            CP_ASYNC16(SH0 + (l*32 + (ch ^ (l & 7)))*16, hb + (size_t)l*Ff + ch*8);
        }
        CP_COMMIT();
    }

    // ---- load U and FW tiles [64 y][256 f] fp32 -> fp16, swizzled ----
    for (int i = tid; i < 64*32; i += 128) {
        int yy = i >> 5, ch = i & 31;
        int gy = ybase + yy;
        float4 u0 = make_float4(0.f,0.f,0.f,0.f), u1 = u0, f0 = u0, f1 = u0;
        if (gy < Yy) {
            const float4* up = (const float4*)(Uw + (size_t)gy*Ff + ch*8);
            const float4* fp = (const float4*)(fw + (size_t)gy*Ff + ch*8);
            u0 = up[0]; u1 = up[1];
            f0 = fp[0]; f1 = fp[1];
        }
        int off = (yy*32 + (ch ^ (yy & 7)))*16;
        uint4 v;
        v.x = pack_h2(u0.x, u0.y);  v.y = pack_h2(u0.z, u0.w);
        v.z = pack_h2(u1.x, u1.y);  v.w = pack_h2(u1.z, u1.w);
        *(uint4*)(sm + off) = v;
        v.x = pack_h2(f0.x, f0.y);  v.y = pack_h2(f0.z, f0.w);
        v.z = pack_h2(f1.x, f1.y);  v.w = pack_h2(f1.z, f1.w);
        *(uint4*)(sm + 32768 + off) = v;
    }

    int rowA = w*16 + (lane & 15);        // ldmatrix A row (y)
    int aX   = lane >> 4;                 // A k-chunk selector
    int nb8  = lane & 7;                  // B ldmatrix row-within-8
    int nHi  = lane >> 4;                 // B: which of the 2 n-tiles
    int bX   = (lane >> 3) & 1;           // B k-chunk selector
    int r0   = w*16 + (lane >> 2);        // accumulator rows r0, r0+8

    float rsum0 = 0.f, rsum1 = 0.f;
    float ydot0 = 0.f, ydot1 = 0.f;

    float* alpha = out + (size_t)Bb*Yy + 1;            // misaligned base: scalar access only
    float* ablk0 = alpha + ((size_t)b*Yy + ybase)*Ll;

    for (int lc = 0; lc < 64; lc++) {
        CP_WAIT0();
        __syncthreads();   // h[lc] visible; alt buffer fully consumed

        // ---- issue next chunk's h load into the alternate buffer ----
        if (lc + 1 < 64) {
            const __half* hb = hbb + (size_t)(lc + 1)*32*Ff;
            u32 dst = SH0 + ((lc + 1) & 1)*16384;
            for (int i = tid; i < 1024; i += 128) {
                int l = i >> 5, ch = i & 31;
                CP_ASYNC16(dst + (l*32 + (ch ^ (l & 7)))*16, hb + (size_t)l*Ff + ch*8);
            }
            CP_COMMIT();
        }

        const u32 SH = SH0 + (lc & 1)*16384;

        // ---- dual GEMM: s = U x h^T,  c = FW x h^T (B ldsm.x4, 2 n-tiles) ----
        float sacc[4][4], cacc[4][4];
#pragma unroll
        for (int nt = 0; nt < 4; nt++)
#pragma unroll
            for (int j = 0; j < 4; j++) { sacc[nt][j] = 0.f; cacc[nt][j] = 0.f; }

#pragma unroll
        for (int ks = 0; ks < 16; ks++) {
            u32 asw = (((ks*2 + aX) ^ (rowA & 7)) << 4);
            u32 a0, a1, a2, a3, q0, q1, q2, q3;
            ldsm4(SU  + rowA*512 + asw, a0, a1, a2, a3);
            ldsm4(SFW + rowA*512 + asw, q0, q1, q2, q3);
#pragma unroll
            for (int ntp = 0; ntp < 2; ntp++) {
                int n = (ntp*2 + nHi)*8 + nb8;
                u32 b0, b1, b2, b3;
                ldsm4(SH + n*512 + (((ks*2 + bX) ^ (n & 7)) << 4), b0, b1, b2, b3);
                MMA(sacc[ntp*2],     a0, a1, a2, a3, b0, b1);
                MMA(cacc[ntp*2],     q0, q1, q2, q3, b0, b1);
                MMA(sacc[ntp*2 + 1], a0, a1, a2, a3, b2, b3);
                MMA(cacc[ntp*2 + 1], q0, q1, q2, q3, b2, b3);
            }
        }

        // ---- e = exp(s); rsum; ydot += e*c; stage e ----
#pragma unroll
        for (int nt = 0; nt < 4; nt++) {
            float e00 = fexp(sacc[nt][0]);
            float e01 = fexp(sacc[nt][1]);
            float e10 = fexp(sacc[nt][2]);
            float e11 = fexp(sacc[nt][3]);
            rsum0 += e00 + e01;
            rsum1 += e10 + e11;
            ydot0 = fmaf(e00, cacc[nt][0], fmaf(e01, cacc[nt][1], ydot0));
            ydot1 = fmaf(e10, cacc[nt][2], fmaf(e11, cacc[nt][3], ydot1));
            int l = nt*8 + (lane & 3)*2;
            esm[(l  )*64 + ((r0   + l    ) & 63)] = e00;
            esm[(l+1)*64 + ((r0   + l + 1) & 63)] = e01;
            esm[(l  )*64 + ((r0+8 + l    ) & 63)] = e10;
            esm[(l+1)*64 + ((r0+8 + l + 1) & 63)] = e11;
        }
        __syncthreads();

        // ---- coalesced scalar alpha stream (unnormalized e) ----
        float* ablk = ablk0 + lc*32;
        for (int i = tid; i < 64*32; i += 128) {
            int yy = i >> 5, l = i & 31;
            if (ybase + yy < Yy)
                ablk[(size_t)yy*Ll + l] = esm[l*64 + ((yy + l) & 63)];
        }
    }

    // ---- reduce rowsums and ydot across the lane quad ----
    rsum0 += __shfl_xor_sync(0xFFFFFFFFu, rsum0, 1);
    rsum0 += __shfl_xor_sync(0xFFFFFFFFu, rsum0, 2);
    rsum1 += __shfl_xor_sync(0xFFFFFFFFu, rsum1, 1);
    rsum1 += __shfl_xor_sync(0xFFFFFFFFu, rsum1, 2);
    ydot0 += __shfl_xor_sync(0xFFFFFFFFu, ydot0, 1);
    ydot0 += __shfl_xor_sync(0xFFFFFFFFu, ydot0, 2);
    ydot1 += __shfl_xor_sync(0xFFFFFFFFu, ydot1, 1);
    ydot1 += __shfl_xor_sync(0xFFFFFFFFu, ydot1, 2);
    __syncthreads();
    if ((lane & 3) == 0) { rsm[r0] = rsum0; rsm[r0 + 8] = rsum1; }

    // ---- yhat ----
    if ((lane & 3) == 0) {
        int gy0 = ybase + r0, gy1 = gy0 + 8;
        if (gy0 < Yy) out[(size_t)b*Yy + gy0] = ydot0 / rsum0 + fb[gy0];
        if (gy1 < Yy) out[(size_t)b*Yy + gy1] = ydot1 / rsum1 + fb[gy1];
    }
    __syncthreads();

    // ---- alpha rescale: alpha = e / Z (scalar, coalesced) ----
    for (int yy = 0; yy < 64; yy++) {
        int g = ybase + yy;
        if (g >= Yy) break;
        float inv = 1.f / rsm[yy];
        float* row = ablk0 + (size_t)yy*Ll;
        for (int l = tid; l < Ll; l += 128)
            row[l] *= inv;
    }
}

// ---------------------------------------------------------------------------
// K3: BCE loss, two-stage deterministic reduction
// ---------------------------------------------------------------------------
__global__ void k_loss1(const float* __restrict__ target, const float* __restrict__ out)
{
    __shared__ float red[256];
    int tid = threadIdx.x;
    float s = 0.f;
    for (int i = blockIdx.x*256 + tid; i < Bb*Yy; i += gridDim.x*256) {
        float yh = out[i];
        float t  = target[i];
        s += fmaxf(yh, 0.f) - yh*t + log1pf(__expf(-fabsf(yh)));
    }
    red[tid] = s;
    __syncthreads();
    for (int st = 128; st > 0; st >>= 1) {
        if (tid < st) red[tid] += red[tid + st];
        __syncthreads();
    }
    if (tid == 0) g_part[blockIdx.x] = red[0];
}

__global__ void k_loss2(float* __restrict__ out)
{
    __shared__ float red[128];
    int tid = threadIdx.x;
    red[tid] = (tid < 70) ? g_part[tid] : 0.f;
    __syncthreads();
    for (int st = 64; st > 0; st >>= 1) {
        if (tid < st) red[tid] += red[tid + st];
        __syncthreads();
    }
    if (tid == 0) out[Bb*Yy] = red[0] / (float)(Bb*Yy);
}

// ---------------------------------------------------------------------------
extern "C" void kernel_launch(void* const* d_in, const int* in_sizes, int n_in,
                              void* d_out, int out_size)
{
    const int*   x      = (const int*)d_in[0];
    const float* target = (const float*)d_in[1];
    const float* embW   = (const float*)d_in[2];
    const float* convw  = (const float*)d_in[3];
    const float* convb  = (const float*)d_in[4];
    const float* Uw     = (const float*)d_in[5];
    const float* fw     = (const float*)d_in[6];
    const float* fb     = (const float*)d_in[7];
    float* out = (float*)d_out;

    cudaFuncSetAttribute(k_attn, cudaFuncAttributeMaxDynamicSharedMemorySize, SMTOT);

    k_transpose<<<(Ff*Ee*KW + 255)/256, 256>>>(convw);
    k_conv<<<dim3(Ll/16, Bb), 256>>>(x, embW, convb);
    k_attn<<<dim3(YT, Bb), 128, SMTOT>>>(Uw, fw, fb, out);
    k_loss1<<<70, 256>>>(target, out);
    k_loss2<<<1, 128>>>(out);
}

// round 15
// speedup vs baseline: 4.3510x; 1.1288x over previous
#include <cuda_runtime.h>
#include <cuda_fp16.h>
#include <math.h>
#include <stdint.h>

// Problem constants
#define Bb    8
#define Ll    2048
#define Ee    100
#define Ff    256
#define KW    9
#define Yy    8921
#define YT    140         // ceil(8921 / 64)

typedef unsigned int u32;

// ---------------------------------------------------------------------------
// Device scratch
// ---------------------------------------------------------------------------
__device__ __half g_wh[KW*Ff*120];                // conv weights fp16 [k][f][e pad 120]
__device__ __half g_hh[(size_t)Bb*Ll*Ff];         // h fp16 [b][l][f]
__device__ float  g_part[256];                    // loss partials

// ---------------------------------------------------------------------------
// Helpers (family-safe PTX only: ldmatrix sm_75+, mma.sync fp16 sm_80+,
//          cp.async sm_80+)
// ---------------------------------------------------------------------------
__device__ __forceinline__ u32 s2u(const void* p) {
    u32 a;
    asm("{ .reg .u64 t; cvta.to.shared.u64 t, %1; cvt.u32.u64 %0, t; }" : "=r"(a) : "l"(p));
    return a;
}
__device__ __forceinline__ void ldsm4(u32 a, u32& r0, u32& r1, u32& r2, u32& r3) {
    asm volatile("ldmatrix.sync.aligned.m8n8.x4.shared.b16 {%0,%1,%2,%3}, [%4];"
                 : "=r"(r0), "=r"(r1), "=r"(r2), "=r"(r3) : "r"(a));
}
#define MMA(d, a0,a1,a2,a3, b0,b1)                                             \
    asm volatile("mma.sync.aligned.m16n8k16.row.col.f32.f16.f16.f32 "          \
        "{%0,%1,%2,%3}, {%4,%5,%6,%7}, {%8,%9}, {%0,%1,%2,%3};"                \
        : "+f"((d)[0]), "+f"((d)[1]), "+f"((d)[2]), "+f"((d)[3])               \
        : "r"(a0), "r"(a1), "r"(a2), "r"(a3), "r"(b0), "r"(b1))

#define CP_ASYNC16(dst, src)                                                   \
    asm volatile("cp.async.cg.shared.global [%0], [%1], 16;"                   \
                 :: "r"(dst), "l"(src) : "memory")
#define CP_COMMIT()  asm volatile("cp.async.commit_group;" ::: "memory")
#define CP_WAIT0()   asm volatile("cp.async.wait_group 0;" ::: "memory")

__device__ __forceinline__ u32 pack_h2(float lo, float hi) {
    __half2 h = __floats2half2_rn(lo, hi);
    return *(u32*)&h;
}

// fast exp on the FMA pipe (rel err ~2e-6 for |x| <= ~30)
__device__ __forceinline__ float fexp(float x) {
    float t = x * 1.4426950408889634f;
    float r = t + 12582912.0f;            // round-to-nearest magic (2^23 * 1.5)
    float i = r - 12582912.0f;
    float f = t - i;
    float s = __int_as_float(0x3f800000 + (__float_as_int(r) << 23));
    float p = 1.3333558146e-3f;
    p = fmaf(p, f, 9.6181291076e-3f);
    p = fmaf(p, f, 5.5504108665e-2f);
    p = fmaf(p, f, 2.4022650696e-1f);
    p = fmaf(p, f, 6.9314718056e-1f);
    p = fmaf(p, f, 1.0f);
    return p * s;
}

// ---------------------------------------------------------------------------
// K0: pack conv_w [F,E,K] fp32 -> g_wh [k][f][e pad 120] fp16
// ---------------------------------------------------------------------------
__global__ void k_wprep(const float* __restrict__ w)
{
    int idx = blockIdx.x * 256 + threadIdx.x;
    if (idx < KW*Ff*120) {
        int k = idx / (Ff*120);
        int r = idx - k*(Ff*120);
        int f = r / 120;
        int e = r - f*120;
        float v = (e < Ee) ? w[f*(Ee*KW) + e*KW + k] : 0.f;
        g_wh[idx] = __float2half_rn(v);
    }
}

// ---------------------------------------------------------------------------
// K1: tensor-core conv: h[l,f] = tanh(bias + sum_k emb[l-4+k,:] W_k[:,f])
//   as 9 accumulated fp16 GEMMs [64l x 112e] x [112e x 256f].
//   A: emb tile [72 rows][120 halves, 240B stride] (odd-16 stride => ldmatrix
//      conflict-free without xor swizzle). conv-k = +k row offset into A.
//   B: g_wh[k] slice [256 f][120 halves, 240B stride], cp.async per conv-k.
// smem: A 17280 | B 61440 | convb 1024 = 79744 B  (+ static toks)
// ---------------------------------------------------------------------------
#define CSM_B   17280
#define CSM_CB  78720
#define CSMTOT  79744

__global__ __launch_bounds__(128, 2) void k_conv(const int* __restrict__ x,
                                                 const float* __restrict__ embW,
                                                 const float* __restrict__ convb)
{
    extern __shared__ char sm[];
    __shared__ int toks[72];
    u32 smb = s2u(sm);
    const u32 SA = smb;
    const u32 SB = smb + CSM_B;
    float* cbs = (float*)(sm + CSM_CB);

    int tid  = threadIdx.x;
    int lane = tid & 31;
    int w    = tid >> 5;                  // warp 0..3
    int b    = blockIdx.y;
    int l0   = blockIdx.x * 64;

    if (tid < 72) {
        int l = l0 - 4 + tid;
        toks[tid] = (l >= 0 && l < Ll) ? x[b*Ll + l] : -1;
    }
    for (int i = tid; i < Ff; i += 128) cbs[i] = convb[i];
    __syncthreads();

    // gather embedding tile -> fp16 A (zero pad cols >= 100, OOB rows)
    for (int idx = tid; idx < 72*60; idx += 128) {
        int row = idx / 60;
        int c2  = idx - row*60;
        int tok = toks[row];
        int e0  = c2*2;
        float v0 = 0.f, v1 = 0.f;
        if (tok >= 0 && e0 < Ee) {
            const float* er = embW + (size_t)tok*Ee;
            v0 = er[e0];
            if (e0 + 1 < Ee) v1 = er[e0 + 1];
        }
        *(u32*)(sm + row*240 + c2*4) = pack_h2(v0, v1);
    }

    int rowA = w*16 + (lane & 15);        // A row (l within tile)
    int aX   = lane >> 4;                 // A k-chunk selector
    int nb8  = lane & 7;                  // B row-within-8
    int nHi  = lane >> 4;                 // B: which of 2 n-tiles
    int bX   = (lane >> 3) & 1;           // B k-chunk selector
    int r0   = w*16 + (lane >> 2);        // output rows r0, r0+8

    float cacc[32][4];
#pragma unroll
    for (int nt = 0; nt < 32; nt++)
#pragma unroll
        for (int j = 0; j < 4; j++) cacc[nt][j] = 0.f;

    for (int ck = 0; ck < KW; ck++) {
        __syncthreads();                  // prev B consumed (first: A gather done)
        const __half* wk = g_wh + ck*(Ff*120);
        for (int i = tid; i < 3840; i += 128)
            CP_ASYNC16(SB + i*16, wk + i*8);
        CP_COMMIT();
        CP_WAIT0();
        __syncthreads();

        u32 abase = SA + (u32)(rowA + ck)*240;
#pragma unroll
        for (int ks = 0; ks < 7; ks++) {
            u32 a0, a1, a2, a3;
            ldsm4(abase + (ks*2 + aX)*16, a0, a1, a2, a3);
#pragma unroll
            for (int ntp = 0; ntp < 16; ntp++) {
                int n = (ntp*2 + nHi)*8 + nb8;
                u32 b0, b1, b2, b3;
                ldsm4(SB + n*240 + (ks*2 + bX)*16, b0, b1, b2, b3);
                MMA(cacc[ntp*2],     a0, a1, a2, a3, b0, b1);
                MMA(cacc[ntp*2 + 1], a0, a1, a2, a3, b2, b3);
            }
        }
    }

    // epilogue: bias + tanh -> fp16 h
    __half* hb = g_hh + ((size_t)b*Ll + l0)*Ff;
#pragma unroll
    for (int nt = 0; nt < 32; nt++) {
        int f0 = nt*8 + (lane & 3)*2;
        float b0 = cbs[f0], b1 = cbs[f0 + 1];
        *(u32*)(hb + (size_t)(r0    )*Ff + f0) =
            pack_h2(tanhf(cacc[nt][0] + b0), tanhf(cacc[nt][1] + b1));
        *(u32*)(hb + (size_t)(r0 + 8)*Ff + f0) =
            pack_h2(tanhf(cacc[nt][2] + b0), tanhf(cacc[nt][3] + b1));
    }
}

// ---------------------------------------------------------------------------
// K2: warp-MMA fused attention (fp16), 2-CTA/SM co-residency layout:
//   64-y tile per CTA, 128 threads (4 warps x 16 rows), 32-l chunks,
//   cp.async double-buffered h, dual GEMM (s = U x h^T, c = FW x h^T),
//   yhat via summation swap, unnormalized-e alpha stream + 1/Z rescale.
// smem/CTA: U 32K | FW 32K | H 2x16K | e-stage 8K | rsm 256B = 106752 B
// ---------------------------------------------------------------------------
#define SMTOT 106752

__global__ __launch_bounds__(128, 2) void k_attn(const float* __restrict__ Uw,
                                                 const float* __restrict__ fw,
                                                 const float* __restrict__ fb,
                                                 float* __restrict__ out)
{
    extern __shared__ char sm[];
    u32 smb  = s2u(sm);
    const u32 SU  = smb;
    const u32 SFW = smb + 32768;
    const u32 SH0 = smb + 65536;          // two 16 KB h buffers
    float* esm = (float*)(sm + 98304);    // e stage [32 l][64 y] xor layout
    float* rsm = (float*)(sm + 106496);   // 64 floats

    int tid  = threadIdx.x;
    int lane = tid & 31;
    int w    = tid >> 5;                   // warp 0..3
    int b    = blockIdx.y;
    int ybase = blockIdx.x * 64;

    const __half* hbb = g_hh + (size_t)b*Ll*Ff;

    // ---- prefetch h chunk 0 into buffer 0 (overlaps U/FW conversion) ----
    {
        const __half* hb = hbb;
        for (int i = tid; i < 1024; i += 128) {
            int l = i >> 5, ch = i & 31;
            CP_ASYNC16(SH0 + (l*32 + (ch ^ (l & 7)))*16, hb + (size_t)l*Ff + ch*8);
        }
        CP_COMMIT();
    }

    // ---- load U and FW tiles [64 y][256 f] fp32 -> fp16, swizzled ----
    for (int i = tid; i < 64*32; i += 128) {
        int yy = i >> 5, ch = i & 31;
        int gy = ybase + yy;
        float4 u0 = make_float4(0.f,0.f,0.f,0.f), u1 = u0, f0 = u0, f1 = u0;
        if (gy < Yy) {
            const float4* up = (const float4*)(Uw + (size_t)gy*Ff + ch*8);
            const float4* fp = (const float4*)(fw + (size_t)gy*Ff + ch*8);
            u0 = up[0]; u1 = up[1];
            f0 = fp[0]; f1 = fp[1];
        }
        int off = (yy*32 + (ch ^ (yy & 7)))*16;
        uint4 v;
        v.x = pack_h2(u0.x, u0.y);  v.y = pack_h2(u0.z, u0.w);
        v.z = pack_h2(u1.x, u1.y);  v.w = pack_h2(u1.z, u1.w);
        *(uint4*)(sm + off) = v;
        v.x = pack_h2(f0.x, f0.y);  v.y = pack_h2(f0.z, f0.w);
        v.z = pack_h2(f1.x, f1.y);  v.w = pack_h2(f1.z, f1.w);
        *(uint4*)(sm + 32768 + off) = v;
    }

    int rowA = w*16 + (lane & 15);        // ldmatrix A row (y)
    int aX   = lane >> 4;                 // A k-chunk selector
    int nb8  = lane & 7;                  // B ldmatrix row-within-8
    int nHi  = lane >> 4;                 // B: which of the 2 n-tiles
    int bX   = (lane >> 3) & 1;           // B k-chunk selector
    int r0   = w*16 + (lane >> 2);        // accumulator rows r0, r0+8

    float rsum0 = 0.f, rsum1 = 0.f;
    float ydot0 = 0.f, ydot1 = 0.f;

    float* alpha = out + (size_t)Bb*Yy + 1;            // misaligned base: scalar access only
    float* ablk0 = alpha + ((size_t)b*Yy + ybase)*Ll;

    for (int lc = 0; lc < 64; lc++) {
        CP_WAIT0();
        __syncthreads();   // h[lc] visible; alt buffer fully consumed

        // ---- issue next chunk's h load into the alternate buffer ----
        if (lc + 1 < 64) {
            const __half* hb = hbb + (size_t)(lc + 1)*32*Ff;
            u32 dst = SH0 + ((lc + 1) & 1)*16384;
            for (int i = tid; i < 1024; i += 128) {
                int l = i >> 5, ch = i & 31;
                CP_ASYNC16(dst + (l*32 + (ch ^ (l & 7)))*16, hb + (size_t)l*Ff + ch*8);
            }
            CP_COMMIT();
        }

        const u32 SH = SH0 + (lc & 1)*16384;

        // ---- dual GEMM: s = U x h^T,  c = FW x h^T (B ldsm.x4, 2 n-tiles) ----
        float sacc[4][4], cacc[4][4];
#pragma unroll
        for (int nt = 0; nt < 4; nt++)
#pragma unroll
            for (int j = 0; j < 4; j++) { sacc[nt][j] = 0.f; cacc[nt][j] = 0.f; }

#pragma unroll
        for (int ks = 0; ks < 16; ks++) {
            u32 asw = (((ks*2 + aX) ^ (rowA & 7)) << 4);
            u32 a0, a1, a2, a3, q0, q1, q2, q3;
            ldsm4(SU  + rowA*512 + asw, a0, a1, a2, a3);
            ldsm4(SFW + rowA*512 + asw, q0, q1, q2, q3);
#pragma unroll
            for (int ntp = 0; ntp < 2; ntp++) {
                int n = (ntp*2 + nHi)*8 + nb8;
                u32 b0, b1, b2, b3;
                ldsm4(SH + n*512 + (((ks*2 + bX) ^ (n & 7)) << 4), b0, b1, b2, b3);
                MMA(sacc[ntp*2],     a0, a1, a2, a3, b0, b1);
                MMA(cacc[ntp*2],     q0, q1, q2, q3, b0, b1);
                MMA(sacc[ntp*2 + 1], a0, a1, a2, a3, b2, b3);
                MMA(cacc[ntp*2 + 1], q0, q1, q2, q3, b2, b3);
            }
        }

        // ---- e = exp(s); rsum; ydot += e*c; stage e ----
#pragma unroll
        for (int nt = 0; nt < 4; nt++) {
            float e00 = fexp(sacc[nt][0]);
            float e01 = fexp(sacc[nt][1]);
            float e10 = fexp(sacc[nt][2]);
            float e11 = fexp(sacc[nt][3]);
            rsum0 += e00 + e01;
            rsum1 += e10 + e11;
            ydot0 = fmaf(e00, cacc[nt][0], fmaf(e01, cacc[nt][1], ydot0));
            ydot1 = fmaf(e10, cacc[nt][2], fmaf(e11, cacc[nt][3], ydot1));
            int l = nt*8 + (lane & 3)*2;
            esm[(l  )*64 + ((r0   + l    ) & 63)] = e00;
            esm[(l+1)*64 + ((r0   + l + 1) & 63)] = e01;
            esm[(l  )*64 + ((r0+8 + l    ) & 63)] = e10;
            esm[(l+1)*64 + ((r0+8 + l + 1) & 63)] = e11;
        }
        __syncthreads();

        // ---- coalesced scalar alpha stream (unnormalized e) ----
        float* ablk = ablk0 + lc*32;
        for (int i = tid; i < 64*32; i += 128) {
            int yy = i >> 5, l = i & 31;
            if (ybase + yy < Yy)
                ablk[(size_t)yy*Ll + l] = esm[l*64 + ((yy + l) & 63)];
        }
    }

    // ---- reduce rowsums and ydot across the lane quad ----
    rsum0 += __shfl_xor_sync(0xFFFFFFFFu, rsum0, 1);
    rsum0 += __shfl_xor_sync(0xFFFFFFFFu, rsum0, 2);
    rsum1 += __shfl_xor_sync(0xFFFFFFFFu, rsum1, 1);
    rsum1 += __shfl_xor_sync(0xFFFFFFFFu, rsum1, 2);
    ydot0 += __shfl_xor_sync(0xFFFFFFFFu, ydot0, 1);
    ydot0 += __shfl_xor_sync(0xFFFFFFFFu, ydot0, 2);
    ydot1 += __shfl_xor_sync(0xFFFFFFFFu, ydot1, 1);
    ydot1 += __shfl_xor_sync(0xFFFFFFFFu, ydot1, 2);
    __syncthreads();
    if ((lane & 3) == 0) { rsm[r0] = rsum0; rsm[r0 + 8] = rsum1; }

    // ---- yhat ----
    if ((lane & 3) == 0) {
        int gy0 = ybase + r0, gy1 = gy0 + 8;
        if (gy0 < Yy) out[(size_t)b*Yy + gy0] = ydot0 / rsum0 + fb[gy0];
        if (gy1 < Yy) out[(size_t)b*Yy + gy1] = ydot1 / rsum1 + fb[gy1];
    }
    __syncthreads();

    // ---- alpha rescale: alpha = e / Z (scalar, coalesced) ----
    for (int yy = 0; yy < 64; yy++) {
        int g = ybase + yy;
        if (g >= Yy) break;
        float inv = 1.f / rsm[yy];
        float* row = ablk0 + (size_t)yy*Ll;
        for (int l = tid; l < Ll; l += 128)
            row[l] *= inv;
    }
}

// ---------------------------------------------------------------------------
// K3: BCE loss, two-stage deterministic reduction
// ---------------------------------------------------------------------------
__global__ void k_loss1(const float* __restrict__ target, const float* __restrict__ out)
{
    __shared__ float red[256];
    int tid = threadIdx.x;
    float s = 0.f;
    for (int i = blockIdx.x*256 + tid; i < Bb*Yy; i += gridDim.x*256) {
        float yh = out[i];
        float t  = target[i];
        s += fmaxf(yh, 0.f) - yh*t + log1pf(__expf(-fabsf(yh)));
    }
    red[tid] = s;
    __syncthreads();
    for (int st = 128; st > 0; st >>= 1) {
        if (tid < st) red[tid] += red[tid + st];
        __syncthreads();
    }
    if (tid == 0) g_part[blockIdx.x] = red[0];
}

__global__ void k_loss2(float* __restrict__ out)
{
    __shared__ float red[128];
    int tid = threadIdx.x;
    red[tid] = (tid < 70) ? g_part[tid] : 0.f;
    __syncthreads();
    for (int st = 64; st > 0; st >>= 1) {
        if (tid < st) red[tid] += red[tid + st];
        __syncthreads();
    }
    if (tid == 0) out[Bb*Yy] = red[0] / (float)(Bb*Yy);
}

// ---------------------------------------------------------------------------
extern "C" void kernel_launch(void* const* d_in, const int* in_sizes, int n_in,
                              void* d_out, int out_size)
{
    const int*   x      = (const int*)d_in[0];
    const float* target = (const float*)d_in[1];
    const float* embW   = (const float*)d_in[2];
    const float* convw  = (const float*)d_in[3];
    const float* convb  = (const float*)d_in[4];
    const float* Uw     = (const float*)d_in[5];
    const float* fw     = (const float*)d_in[6];
    const float* fb     = (const float*)d_in[7];
    float* out = (float*)d_out;

    cudaFuncSetAttribute(k_conv, cudaFuncAttributeMaxDynamicSharedMemorySize, CSMTOT);
    cudaFuncSetAttribute(k_attn, cudaFuncAttributeMaxDynamicSharedMemorySize, SMTOT);

    k_wprep<<<(KW*Ff*120 + 255)/256, 256>>>(convw);
    k_conv<<<dim3(Ll/64, Bb), 128, CSMTOT>>>(x, embW, convb);
    k_attn<<<dim3(YT, Bb), 128, SMTOT>>>(Uw, fw, fb, out);
    k_loss1<<<70, 256>>>(target, out);
    k_loss2<<<1, 128>>>(out);
}

// round 16
// speedup vs baseline: 4.4149x; 1.0147x over previous
#include <cuda_runtime.h>
#include <cuda_fp16.h>
#include <math.h>
#include <stdint.h>

// Problem constants
#define Bb    8
#define Ll    2048
#define Ee    100
#define Ff    256
#define KW    9
#define Yy    8921
#define YT    140         // ceil(8921 / 64)

typedef unsigned int u32;

// ---------------------------------------------------------------------------
// Device scratch
// ---------------------------------------------------------------------------
__device__ __half g_wh[KW*Ff*120];                // conv weights fp16 [k][f][e pad 120]
__device__ __half g_hh[(size_t)Bb*Ll*Ff];         // h fp16 [b][l][f]
__device__ float  g_part[256];                    // loss partials

// ---------------------------------------------------------------------------
// Helpers (family-safe PTX only: ldmatrix sm_75+, mma.sync fp16 sm_80+,
//          cp.async sm_80+)
// ---------------------------------------------------------------------------
__device__ __forceinline__ u32 s2u(const void* p) {
    u32 a;
    asm("{ .reg .u64 t; cvta.to.shared.u64 t, %1; cvt.u32.u64 %0, t; }" : "=r"(a) : "l"(p));
    return a;
}
__device__ __forceinline__ void ldsm4(u32 a, u32& r0, u32& r1, u32& r2, u32& r3) {
    asm volatile("ldmatrix.sync.aligned.m8n8.x4.shared.b16 {%0,%1,%2,%3}, [%4];"
                 : "=r"(r0), "=r"(r1), "=r"(r2), "=r"(r3) : "r"(a));
}
#define MMA(d, a0,a1,a2,a3, b0,b1)                                             \
    asm volatile("mma.sync.aligned.m16n8k16.row.col.f32.f16.f16.f32 "          \
        "{%0,%1,%2,%3}, {%4,%5,%6,%7}, {%8,%9}, {%0,%1,%2,%3};"                \
        : "+f"((d)[0]), "+f"((d)[1]), "+f"((d)[2]), "+f"((d)[3])               \
        : "r"(a0), "r"(a1), "r"(a2), "r"(a3), "r"(b0), "r"(b1))

#define CP_ASYNC16(dst, src)                                                   \
    asm volatile("cp.async.cg.shared.global [%0], [%1], 16;"                   \
                 :: "r"(dst), "l"(src) : "memory")
#define CP_COMMIT()  asm volatile("cp.async.commit_group;" ::: "memory")
#define CP_WAIT0()   asm volatile("cp.async.wait_group 0;" ::: "memory")

__device__ __forceinline__ u32 pack_h2(float lo, float hi) {
    __half2 h = __floats2half2_rn(lo, hi);
    return *(u32*)&h;
}

// fast exp on the FMA pipe (rel err ~2e-6 for |x| <= ~30)
__device__ __forceinline__ float fexp(float x) {
    float t = x * 1.4426950408889634f;
    float r = t + 12582912.0f;            // round-to-nearest magic (2^23 * 1.5)
    float i = r - 12582912.0f;
    float f = t - i;
    float s = __int_as_float(0x3f800000 + (__float_as_int(r) << 23));
    float p = 1.3333558146e-3f;
    p = fmaf(p, f, 9.6181291076e-3f);
    p = fmaf(p, f, 5.5504108665e-2f);
    p = fmaf(p, f, 2.4022650696e-1f);
    p = fmaf(p, f, 6.9314718056e-1f);
    p = fmaf(p, f, 1.0f);
    return p * s;
}

// ---------------------------------------------------------------------------
// K0: pack conv_w [F,E,K] fp32 -> g_wh [k][f][e pad 120] fp16
// ---------------------------------------------------------------------------
__global__ void k_wprep(const float* __restrict__ w)
{
    int idx = blockIdx.x * 256 + threadIdx.x;
    if (idx < KW*Ff*120) {
        int k = idx / (Ff*120);
        int r = idx - k*(Ff*120);
        int f = r / 120;
        int e = r - f*120;
        float v = (e < Ee) ? w[f*(Ee*KW) + e*KW + k] : 0.f;
        g_wh[idx] = __float2half_rn(v);
    }
}

// ---------------------------------------------------------------------------
// K1: tensor-core conv: h[l,f] = tanh(bias + sum_k emb[l-4+k,:] W_k[:,f])
//   as 9 accumulated fp16 GEMMs [64l x 112e] x [112e x 256f].
// smem: A 17280 | B 61440 | convb 1024 = 79744 B  (+ static toks)
// ---------------------------------------------------------------------------
#define CSM_B   17280
#define CSM_CB  78720
#define CSMTOT  79744

__global__ __launch_bounds__(128, 2) void k_conv(const int* __restrict__ x,
                                                 const float* __restrict__ embW,
                                                 const float* __restrict__ convb)
{
    extern __shared__ char sm[];
    __shared__ int toks[72];
    u32 smb = s2u(sm);
    const u32 SA = smb;
    const u32 SB = smb + CSM_B;
    float* cbs = (float*)(sm + CSM_CB);

    int tid  = threadIdx.x;
    int lane = tid & 31;
    int w    = tid >> 5;                  // warp 0..3
    int b    = blockIdx.y;
    int l0   = blockIdx.x * 64;

    if (tid < 72) {
        int l = l0 - 4 + tid;
        toks[tid] = (l >= 0 && l < Ll) ? x[b*Ll + l] : -1;
    }
    for (int i = tid; i < Ff; i += 128) cbs[i] = convb[i];
    __syncthreads();

    // gather embedding tile -> fp16 A (zero pad cols >= 100, OOB rows)
    for (int idx = tid; idx < 72*60; idx += 128) {
        int row = idx / 60;
        int c2  = idx - row*60;
        int tok = toks[row];
        int e0  = c2*2;
        float v0 = 0.f, v1 = 0.f;
        if (tok >= 0 && e0 < Ee) {
            const float* er = embW + (size_t)tok*Ee;
            v0 = er[e0];
            if (e0 + 1 < Ee) v1 = er[e0 + 1];
        }
        *(u32*)(sm + row*240 + c2*4) = pack_h2(v0, v1);
    }

    int rowA = w*16 + (lane & 15);        // A row (l within tile)
    int aX   = lane >> 4;                 // A k-chunk selector
    int nb8  = lane & 7;                  // B row-within-8
    int nHi  = lane >> 4;                 // B: which of 2 n-tiles
    int bX   = (lane >> 3) & 1;           // B k-chunk selector
    int r0   = w*16 + (lane >> 2);        // output rows r0, r0+8

    float cacc[32][4];
#pragma unroll
    for (int nt = 0; nt < 32; nt++)
#pragma unroll
        for (int j = 0; j < 4; j++) cacc[nt][j] = 0.f;

    for (int ck = 0; ck < KW; ck++) {
        __syncthreads();                  // prev B consumed (first: A gather done)
        const __half* wk = g_wh + ck*(Ff*120);
        for (int i = tid; i < 3840; i += 128)
            CP_ASYNC16(SB + i*16, wk + i*8);
        CP_COMMIT();
        CP_WAIT0();
        __syncthreads();

        u32 abase = SA + (u32)(rowA + ck)*240;
#pragma unroll
        for (int ks = 0; ks < 7; ks++) {
            u32 a0, a1, a2, a3;
            ldsm4(abase + (ks*2 + aX)*16, a0, a1, a2, a3);
#pragma unroll
            for (int ntp = 0; ntp < 16; ntp++) {
                int n = (ntp*2 + nHi)*8 + nb8;
                u32 b0, b1, b2, b3;
                ldsm4(SB + n*240 + (ks*2 + bX)*16, b0, b1, b2, b3);
                MMA(cacc[ntp*2],     a0, a1, a2, a3, b0, b1);
                MMA(cacc[ntp*2 + 1], a0, a1, a2, a3, b2, b3);
            }
        }
    }

    // epilogue: bias + tanh -> fp16 h
    __half* hb = g_hh + ((size_t)b*Ll + l0)*Ff;
#pragma unroll
    for (int nt = 0; nt < 32; nt++) {
        int f0 = nt*8 + (lane & 3)*2;
        float b0 = cbs[f0], b1 = cbs[f0 + 1];
        *(u32*)(hb + (size_t)(r0    )*Ff + f0) =
            pack_h2(tanhf(cacc[nt][0] + b0), tanhf(cacc[nt][1] + b1));
        *(u32*)(hb + (size_t)(r0 + 8)*Ff + f0) =
            pack_h2(tanhf(cacc[nt][2] + b0), tanhf(cacc[nt][3] + b1));
    }
}

// ---------------------------------------------------------------------------
// K2: warp-MMA fused attention (fp16), 2-CTA/SM co-residency layout.
//   NEW: U/FW A-fragments are loop-invariant -> hoisted into registers once
//   (au/aq, 128 regs); chunk loop does only B-side (h) ldsm + MMA.
// smem/CTA: U 32K | FW 32K | H 2x16K | e-stage 8K | rsm 256B = 106752 B
// ---------------------------------------------------------------------------
#define SMTOT 106752

__global__ __launch_bounds__(128, 2) void k_attn(const float* __restrict__ Uw,
                                                 const float* __restrict__ fw,
                                                 const float* __restrict__ fb,
                                                 float* __restrict__ out)
{
    extern __shared__ char sm[];
    u32 smb  = s2u(sm);
    const u32 SU  = smb;
    const u32 SFW = smb + 32768;
    const u32 SH0 = smb + 65536;          // two 16 KB h buffers
    float* esm = (float*)(sm + 98304);    // e stage [32 l][64 y] xor layout
    float* rsm = (float*)(sm + 106496);   // 64 floats

    int tid  = threadIdx.x;
    int lane = tid & 31;
    int w    = tid >> 5;                   // warp 0..3
    int b    = blockIdx.y;
    int ybase = blockIdx.x * 64;

    const __half* hbb = g_hh + (size_t)b*Ll*Ff;

    // ---- prefetch h chunk 0 into buffer 0 (overlaps U/FW conversion) ----
    {
        const __half* hb = hbb;
        for (int i = tid; i < 1024; i += 128) {
            int l = i >> 5, ch = i & 31;
            CP_ASYNC16(SH0 + (l*32 + (ch ^ (l & 7)))*16, hb + (size_t)l*Ff + ch*8);
        }
        CP_COMMIT();
    }

    // ---- load U and FW tiles [64 y][256 f] fp32 -> fp16, swizzled ----
    for (int i = tid; i < 64*32; i += 128) {
        int yy = i >> 5, ch = i & 31;
        int gy = ybase + yy;
        float4 u0 = make_float4(0.f,0.f,0.f,0.f), u1 = u0, f0 = u0, f1 = u0;
        if (gy < Yy) {
            const float4* up = (const float4*)(Uw + (size_t)gy*Ff + ch*8);
            const float4* fp = (const float4*)(fw + (size_t)gy*Ff + ch*8);
            u0 = up[0]; u1 = up[1];
            f0 = fp[0]; f1 = fp[1];
        }
        int off = (yy*32 + (ch ^ (yy & 7)))*16;
        uint4 v;
        v.x = pack_h2(u0.x, u0.y);  v.y = pack_h2(u0.z, u0.w);
        v.z = pack_h2(u1.x, u1.y);  v.w = pack_h2(u1.z, u1.w);
        *(uint4*)(sm + off) = v;
        v.x = pack_h2(f0.x, f0.y);  v.y = pack_h2(f0.z, f0.w);
        v.z = pack_h2(f1.x, f1.y);  v.w = pack_h2(f1.z, f1.w);
        *(uint4*)(sm + 32768 + off) = v;
    }

    int rowA = w*16 + (lane & 15);        // ldmatrix A row (y)
    int aX   = lane >> 4;                 // A k-chunk selector
    int nb8  = lane & 7;                  // B ldmatrix row-within-8
    int nHi  = lane >> 4;                 // B: which of the 2 n-tiles
    int bX   = (lane >> 3) & 1;           // B k-chunk selector
    int r0   = w*16 + (lane >> 2);        // accumulator rows r0, r0+8

    __syncthreads();                      // SU/SFW fully written

    // ---- hoist loop-invariant A fragments (U, FW) into registers ----
    u32 au[16][4], aq[16][4];
#pragma unroll
    for (int ks = 0; ks < 16; ks++) {
        u32 asw = (((ks*2 + aX) ^ (rowA & 7)) << 4);
        ldsm4(SU  + rowA*512 + asw, au[ks][0], au[ks][1], au[ks][2], au[ks][3]);
        ldsm4(SFW + rowA*512 + asw, aq[ks][0], aq[ks][1], aq[ks][2], aq[ks][3]);
    }

    float rsum0 = 0.f, rsum1 = 0.f;
    float ydot0 = 0.f, ydot1 = 0.f;

    float* alpha = out + (size_t)Bb*Yy + 1;            // misaligned base: scalar access only
    float* ablk0 = alpha + ((size_t)b*Yy + ybase)*Ll;

    for (int lc = 0; lc < 64; lc++) {
        CP_WAIT0();
        __syncthreads();   // h[lc] visible; alt buffer fully consumed

        // ---- issue next chunk's h load into the alternate buffer ----
        if (lc + 1 < 64) {
            const __half* hb = hbb + (size_t)(lc + 1)*32*Ff;
            u32 dst = SH0 + ((lc + 1) & 1)*16384;
            for (int i = tid; i < 1024; i += 128) {
                int l = i >> 5, ch = i & 31;
                CP_ASYNC16(dst + (l*32 + (ch ^ (l & 7)))*16, hb + (size_t)l*Ff + ch*8);
            }
            CP_COMMIT();
        }

        const u32 SH = SH0 + (lc & 1)*16384;

        // ---- dual GEMM: s = U x h^T,  c = FW x h^T (B ldsm.x4, 2 n-tiles) ----
        float sacc[4][4], cacc[4][4];
#pragma unroll
        for (int nt = 0; nt < 4; nt++)
#pragma unroll
            for (int j = 0; j < 4; j++) { sacc[nt][j] = 0.f; cacc[nt][j] = 0.f; }

#pragma unroll
        for (int ks = 0; ks < 16; ks++) {
#pragma unroll
            for (int ntp = 0; ntp < 2; ntp++) {
                int n = (ntp*2 + nHi)*8 + nb8;
                u32 b0, b1, b2, b3;
                ldsm4(SH + n*512 + (((ks*2 + bX) ^ (n & 7)) << 4), b0, b1, b2, b3);
                MMA(sacc[ntp*2],     au[ks][0], au[ks][1], au[ks][2], au[ks][3], b0, b1);
                MMA(cacc[ntp*2],     aq[ks][0], aq[ks][1], aq[ks][2], aq[ks][3], b0, b1);
                MMA(sacc[ntp*2 + 1], au[ks][0], au[ks][1], au[ks][2], au[ks][3], b2, b3);
                MMA(cacc[ntp*2 + 1], aq[ks][0], aq[ks][1], aq[ks][2], aq[ks][3], b2, b3);
            }
        }

        // ---- e = exp(s); rsum; ydot += e*c; stage e ----
#pragma unroll
        for (int nt = 0; nt < 4; nt++) {
            float e00 = fexp(sacc[nt][0]);
            float e01 = fexp(sacc[nt][1]);
            float e10 = fexp(sacc[nt][2]);
            float e11 = fexp(sacc[nt][3]);
            rsum0 += e00 + e01;
            rsum1 += e10 + e11;
            ydot0 = fmaf(e00, cacc[nt][0], fmaf(e01, cacc[nt][1], ydot0));
            ydot1 = fmaf(e10, cacc[nt][2], fmaf(e11, cacc[nt][3], ydot1));
            int l = nt*8 + (lane & 3)*2;
            esm[(l  )*64 + ((r0   + l    ) & 63)] = e00;
            esm[(l+1)*64 + ((r0   + l + 1) & 63)] = e01;
            esm[(l  )*64 + ((r0+8 + l    ) & 63)] = e10;
            esm[(l+1)*64 + ((r0+8 + l + 1) & 63)] = e11;
        }
        __syncthreads();

        // ---- coalesced scalar alpha stream (unnormalized e) ----
        float* ablk = ablk0 + lc*32;
        for (int i = tid; i < 64*32; i += 128) {
            int yy = i >> 5, l = i & 31;
            if (ybase + yy < Yy)
                ablk[(size_t)yy*Ll + l] = esm[l*64 + ((yy + l) & 63)];
        }
    }

    // ---- reduce rowsums and ydot across the lane quad ----
    rsum0 += __shfl_xor_sync(0xFFFFFFFFu, rsum0, 1);
    rsum0 += __shfl_xor_sync(0xFFFFFFFFu, rsum0, 2);
    rsum1 += __shfl_xor_sync(0xFFFFFFFFu, rsum1, 1);
    rsum1 += __shfl_xor_sync(0xFFFFFFFFu, rsum1, 2);
    ydot0 += __shfl_xor_sync(0xFFFFFFFFu, ydot0, 1);
    ydot0 += __shfl_xor_sync(0xFFFFFFFFu, ydot0, 2);
    ydot1 += __shfl_xor_sync(0xFFFFFFFFu, ydot1, 1);
    ydot1 += __shfl_xor_sync(0xFFFFFFFFu, ydot1, 2);
    __syncthreads();
    if ((lane & 3) == 0) { rsm[r0] = rsum0; rsm[r0 + 8] = rsum1; }

    // ---- yhat ----
    if ((lane & 3) == 0) {
        int gy0 = ybase + r0, gy1 = gy0 + 8;
        if (gy0 < Yy) out[(size_t)b*Yy + gy0] = ydot0 / rsum0 + fb[gy0];
        if (gy1 < Yy) out[(size_t)b*Yy + gy1] = ydot1 / rsum1 + fb[gy1];
    }
    __syncthreads();

    // ---- alpha rescale: alpha = e / Z (scalar, coalesced) ----
    for (int yy = 0; yy < 64; yy++) {
        int g = ybase + yy;
        if (g >= Yy) break;
        float inv = 1.f / rsm[yy];
        float* row = ablk0 + (size_t)yy*Ll;
        for (int l = tid; l < Ll; l += 128)
            row[l] *= inv;
    }
}

// ---------------------------------------------------------------------------
// K3: BCE loss, two-stage deterministic reduction
// ---------------------------------------------------------------------------
__global__ void k_loss1(const float* __restrict__ target, const float* __restrict__ out)
{
    __shared__ float red[256];
    int tid = threadIdx.x;
    float s = 0.f;
    for (int i = blockIdx.x*256 + tid; i < Bb*Yy; i += gridDim.x*256) {
        float yh = out[i];
        float t  = target[i];
        s += fmaxf(yh, 0.f) - yh*t + log1pf(__expf(-fabsf(yh)));
    }
    red[tid] = s;
    __syncthreads();
    for (int st = 128; st > 0; st >>= 1) {
        if (tid < st) red[tid] += red[tid + st];
        __syncthreads();
    }
    if (tid == 0) g_part[blockIdx.x] = red[0];
}

__global__ void k_loss2(float* __restrict__ out)
{
    __shared__ float red[128];
    int tid = threadIdx.x;
    red[tid] = (tid < 70) ? g_part[tid] : 0.f;
    __syncthreads();
    for (int st = 64; st > 0; st >>= 1) {
        if (tid < st) red[tid] += red[tid + st];
        __syncthreads();
    }
    if (tid == 0) out[Bb*Yy] = red[0] / (float)(Bb*Yy);
}

// ---------------------------------------------------------------------------
extern "C" void kernel_launch(void* const* d_in, const int* in_sizes, int n_in,
                              void* d_out, int out_size)
{
    const int*   x      = (const int*)d_in[0];
    const float* target = (const float*)d_in[1];
    const float* embW   = (const float*)d_in[2];
    const float* convw  = (const float*)d_in[3];
    const float* convb  = (const float*)d_in[4];
    const float* Uw     = (const float*)d_in[5];
    const float* fw     = (const float*)d_in[6];
    const float* fb     = (const float*)d_in[7];
    float* out = (float*)d_out;

    cudaFuncSetAttribute(k_conv, cudaFuncAttributeMaxDynamicSharedMemorySize, CSMTOT);
    cudaFuncSetAttribute(k_attn, cudaFuncAttributeMaxDynamicSharedMemorySize, SMTOT);

    k_wprep<<<(KW*Ff*120 + 255)/256, 256>>>(convw);
    k_conv<<<dim3(Ll/64, Bb), 128, CSMTOT>>>(x, embW, convb);
    k_attn<<<dim3(YT, Bb), 128, SMTOT>>>(Uw, fw, fb, out);
    k_loss1<<<70, 256>>>(target, out);
    k_loss2<<<1, 128>>>(out);
}

// round 17
// speedup vs baseline: 4.9601x; 1.1235x over previous
#include <cuda_runtime.h>
#include <cuda_fp16.h>
#include <math.h>
#include <stdint.h>

// Problem constants
#define Bb    8
#define Ll    2048
#define Ee    100
#define Ff    256
#define KW    9
#define Yy    8921
#define YT    140         // ceil(8921 / 64)

typedef unsigned int u32;

// ---------------------------------------------------------------------------
// Device scratch
// ---------------------------------------------------------------------------
__device__ __half g_wh[KW*Ff*120];                // conv weights fp16 [k][f][e pad 120]
__device__ __half g_hh[(size_t)Bb*Ll*Ff];         // h fp16 [b][l][f]
__device__ float  g_part[256];                    // loss partials

// ---------------------------------------------------------------------------
// Helpers (family-safe PTX only: ldmatrix sm_75+, mma.sync fp16 sm_80+,
//          cp.async sm_80+)
// ---------------------------------------------------------------------------
__device__ __forceinline__ u32 s2u(const void* p) {
    u32 a;
    asm("{ .reg .u64 t; cvta.to.shared.u64 t, %1; cvt.u32.u64 %0, t; }" : "=r"(a) : "l"(p));
    return a;
}
__device__ __forceinline__ void ldsm4(u32 a, u32& r0, u32& r1, u32& r2, u32& r3) {
    asm volatile("ldmatrix.sync.aligned.m8n8.x4.shared.b16 {%0,%1,%2,%3}, [%4];"
                 : "=r"(r0), "=r"(r1), "=r"(r2), "=r"(r3) : "r"(a));
}
#define MMA(d, a0,a1,a2,a3, b0,b1)                                             \
    asm volatile("mma.sync.aligned.m16n8k16.row.col.f32.f16.f16.f32 "          \
        "{%0,%1,%2,%3}, {%4,%5,%6,%7}, {%8,%9}, {%0,%1,%2,%3};"                \
        : "+f"((d)[0]), "+f"((d)[1]), "+f"((d)[2]), "+f"((d)[3])               \
        : "r"(a0), "r"(a1), "r"(a2), "r"(a3), "r"(b0), "r"(b1))

#define CP_ASYNC16(dst, src)                                                   \
    asm volatile("cp.async.cg.shared.global [%0], [%1], 16;"                   \
                 :: "r"(dst), "l"(src) : "memory")
#define CP_COMMIT()  asm volatile("cp.async.commit_group;" ::: "memory")
#define CP_WAIT0()   asm volatile("cp.async.wait_group 0;" ::: "memory")

__device__ __forceinline__ u32 pack_h2(float lo, float hi) {
    __half2 h = __floats2half2_rn(lo, hi);
    return *(u32*)&h;
}

// fast exp on the FMA pipe (rel err ~2e-6 for |x| <= ~30)
__device__ __forceinline__ float fexp(float x) {
    float t = x * 1.4426950408889634f;
    float r = t + 12582912.0f;            // round-to-nearest magic (2^23 * 1.5)
    float i = r - 12582912.0f;
    float f = t - i;
    float s = __int_as_float(0x3f800000 + (__float_as_int(r) << 23));
    float p = 1.3333558146e-3f;
    p = fmaf(p, f, 9.6181291076e-3f);
    p = fmaf(p, f, 5.5504108665e-2f);
    p = fmaf(p, f, 2.4022650696e-1f);
    p = fmaf(p, f, 6.9314718056e-1f);
    p = fmaf(p, f, 1.0f);
    return p * s;
}

// ---------------------------------------------------------------------------
// K0: pack conv_w [F,E,K] fp32 -> g_wh [k][f][e pad 120] fp16
// ---------------------------------------------------------------------------
__global__ void k_wprep(const float* __restrict__ w)
{
    int idx = blockIdx.x * 256 + threadIdx.x;
    if (idx < KW*Ff*120) {
        int k = idx / (Ff*120);
        int r = idx - k*(Ff*120);
        int f = r / 120;
        int e = r - f*120;
        float v = (e < Ee) ? w[f*(Ee*KW) + e*KW + k] : 0.f;
        g_wh[idx] = __float2half_rn(v);
    }
}

// ---------------------------------------------------------------------------
// K1: tensor-core conv: h[l,f] = tanh(bias + sum_k emb[l-4+k,:] W_k[:,f])
//   as 9 accumulated fp16 GEMMs [64l x 112e] x [112e x 256f].
// smem: A 17280 | B 61440 | convb 1024 = 79744 B  (+ static toks)
// ---------------------------------------------------------------------------
#define CSM_B   17280
#define CSM_CB  78720
#define CSMTOT  79744

__global__ __launch_bounds__(128, 2) void k_conv(const int* __restrict__ x,
                                                 const float* __restrict__ embW,
                                                 const float* __restrict__ convb)
{
    extern __shared__ char sm[];
    __shared__ int toks[72];
    u32 smb = s2u(sm);
    const u32 SA = smb;
    const u32 SB = smb + CSM_B;
    float* cbs = (float*)(sm + CSM_CB);

    int tid  = threadIdx.x;
    int lane = tid & 31;
    int w    = tid >> 5;                  // warp 0..3
    int b    = blockIdx.y;
    int l0   = blockIdx.x * 64;

    if (tid < 72) {
        int l = l0 - 4 + tid;
        toks[tid] = (l >= 0 && l < Ll) ? x[b*Ll + l] : -1;
    }
    for (int i = tid; i < Ff; i += 128) cbs[i] = convb[i];
    __syncthreads();

    // gather embedding tile -> fp16 A (zero pad cols >= 100, OOB rows)
    for (int idx = tid; idx < 72*60; idx += 128) {
        int row = idx / 60;
        int c2  = idx - row*60;
        int tok = toks[row];
        int e0  = c2*2;
        float v0 = 0.f, v1 = 0.f;
        if (tok >= 0 && e0 < Ee) {
            const float* er = embW + (size_t)tok*Ee;
            v0 = er[e0];
            if (e0 + 1 < Ee) v1 = er[e0 + 1];
        }
        *(u32*)(sm + row*240 + c2*4) = pack_h2(v0, v1);
    }

    int rowA = w*16 + (lane & 15);        // A row (l within tile)
    int aX   = lane >> 4;                 // A k-chunk selector
    int nb8  = lane & 7;                  // B row-within-8
    int nHi  = lane >> 4;                 // B: which of 2 n-tiles
    int bX   = (lane >> 3) & 1;           // B k-chunk selector
    int r0   = w*16 + (lane >> 2);        // output rows r0, r0+8

    float cacc[32][4];
#pragma unroll
    for (int nt = 0; nt < 32; nt++)
#pragma unroll
        for (int j = 0; j < 4; j++) cacc[nt][j] = 0.f;

    for (int ck = 0; ck < KW; ck++) {
        __syncthreads();                  // prev B consumed (first: A gather done)
        const __half* wk = g_wh + ck*(Ff*120);
        for (int i = tid; i < 3840; i += 128)
            CP_ASYNC16(SB + i*16, wk + i*8);
        CP_COMMIT();
        CP_WAIT0();
        __syncthreads();

        u32 abase = SA + (u32)(rowA + ck)*240;
#pragma unroll
        for (int ks = 0; ks < 7; ks++) {
            u32 a0, a1, a2, a3;
            ldsm4(abase + (ks*2 + aX)*16, a0, a1, a2, a3);
#pragma unroll
            for (int ntp = 0; ntp < 16; ntp++) {
                int n = (ntp*2 + nHi)*8 + nb8;
                u32 b0, b1, b2, b3;
                ldsm4(SB + n*240 + (ks*2 + bX)*16, b0, b1, b2, b3);
                MMA(cacc[ntp*2],     a0, a1, a2, a3, b0, b1);
                MMA(cacc[ntp*2 + 1], a0, a1, a2, a3, b2, b3);
            }
        }
    }

    // epilogue: bias + tanh -> fp16 h
    __half* hb = g_hh + ((size_t)b*Ll + l0)*Ff;
#pragma unroll
    for (int nt = 0; nt < 32; nt++) {
        int f0 = nt*8 + (lane & 3)*2;
        float b0 = cbs[f0], b1 = cbs[f0 + 1];
        *(u32*)(hb + (size_t)(r0    )*Ff + f0) =
            pack_h2(tanhf(cacc[nt][0] + b0), tanhf(cacc[nt][1] + b1));
        *(u32*)(hb + (size_t)(r0 + 8)*Ff + f0) =
            pack_h2(tanhf(cacc[nt][2] + b0), tanhf(cacc[nt][3] + b1));
    }
}

// ---------------------------------------------------------------------------
// K2: warp-MMA fused attention (fp16), 3-CTA/SM co-residency:
//   U hoisted to registers via staging through the FW smem buffer, so smem
//   is only FW 32K | H 2x16K | e-stage 8K | rsm 256B = 73984 B -> 3 CTAs/SM.
//   s-GEMM uses register A (au); c-GEMM ldsm's FW per chunk.
// ---------------------------------------------------------------------------
#define SMTOT 73984
#define AOFF_E 65536
#define AOFF_R 73728

__global__ __launch_bounds__(128, 3) void k_attn(const float* __restrict__ Uw,
                                                 const float* __restrict__ fw,
                                                 const float* __restrict__ fb,
                                                 float* __restrict__ out)
{
    extern __shared__ char sm[];
    u32 smb  = s2u(sm);
    const u32 SFW = smb;                  // staging (U first, then FW)
    const u32 SH0 = smb + 32768;          // two 16 KB h buffers
    float* esm = (float*)(sm + AOFF_E);   // e stage [32 l][64 y] xor layout
    float* rsm = (float*)(sm + AOFF_R);   // 64 floats

    int tid  = threadIdx.x;
    int lane = tid & 31;
    int w    = tid >> 5;                   // warp 0..3
    int b    = blockIdx.y;
    int ybase = blockIdx.x * 64;

    const __half* hbb = g_hh + (size_t)b*Ll*Ff;

    // ---- prefetch h chunk 0 into buffer 0 ----
    {
        const __half* hb = hbb;
        for (int i = tid; i < 1024; i += 128) {
            int l = i >> 5, ch = i & 31;
            CP_ASYNC16(SH0 + (l*32 + (ch ^ (l & 7)))*16, hb + (size_t)l*Ff + ch*8);
        }
        CP_COMMIT();
    }

    int rowA = w*16 + (lane & 15);        // ldmatrix A row (y)
    int aX   = lane >> 4;                 // A k-chunk selector
    int nb8  = lane & 7;                  // B ldmatrix row-within-8
    int nHi  = lane >> 4;                 // B: which of the 2 n-tiles
    int bX   = (lane >> 3) & 1;           // B k-chunk selector
    int r0   = w*16 + (lane >> 2);        // accumulator rows r0, r0+8

    // ---- stage U through SFW, hoist fragments to registers ----
    for (int i = tid; i < 64*32; i += 128) {
        int yy = i >> 5, ch = i & 31;
        int gy = ybase + yy;
        float4 u0 = make_float4(0.f,0.f,0.f,0.f), u1 = u0;
        if (gy < Yy) {
            const float4* up = (const float4*)(Uw + (size_t)gy*Ff + ch*8);
            u0 = up[0]; u1 = up[1];
        }
        uint4 v;
        v.x = pack_h2(u0.x, u0.y);  v.y = pack_h2(u0.z, u0.w);
        v.z = pack_h2(u1.x, u1.y);  v.w = pack_h2(u1.z, u1.w);
        *(uint4*)(sm + (yy*32 + (ch ^ (yy & 7)))*16) = v;
    }
    __syncthreads();

    u32 au[16][4];
#pragma unroll
    for (int ks = 0; ks < 16; ks++) {
        u32 asw = (((ks*2 + aX) ^ (rowA & 7)) << 4);
        ldsm4(SFW + rowA*512 + asw, au[ks][0], au[ks][1], au[ks][2], au[ks][3]);
    }
    __syncthreads();                      // all warps done reading U

    // ---- now load FW into the same buffer ----
    for (int i = tid; i < 64*32; i += 128) {
        int yy = i >> 5, ch = i & 31;
        int gy = ybase + yy;
        float4 f0 = make_float4(0.f,0.f,0.f,0.f), f1 = f0;
        if (gy < Yy) {
            const float4* fp = (const float4*)(fw + (size_t)gy*Ff + ch*8);
            f0 = fp[0]; f1 = fp[1];
        }
        uint4 v;
        v.x = pack_h2(f0.x, f0.y);  v.y = pack_h2(f0.z, f0.w);
        v.z = pack_h2(f1.x, f1.y);  v.w = pack_h2(f1.z, f1.w);
        *(uint4*)(sm + (yy*32 + (ch ^ (yy & 7)))*16) = v;
    }

    float rsum0 = 0.f, rsum1 = 0.f;
    float ydot0 = 0.f, ydot1 = 0.f;

    float* alpha = out + (size_t)Bb*Yy + 1;            // misaligned base: scalar access only
    float* ablk0 = alpha + ((size_t)b*Yy + ybase)*Ll;

    for (int lc = 0; lc < 64; lc++) {
        CP_WAIT0();
        __syncthreads();   // h[lc] + FW visible; alt buffer fully consumed

        // ---- issue next chunk's h load into the alternate buffer ----
        if (lc + 1 < 64) {
            const __half* hb = hbb + (size_t)(lc + 1)*32*Ff;
            u32 dst = SH0 + ((lc + 1) & 1)*16384;
            for (int i = tid; i < 1024; i += 128) {
                int l = i >> 5, ch = i & 31;
                CP_ASYNC16(dst + (l*32 + (ch ^ (l & 7)))*16, hb + (size_t)l*Ff + ch*8);
            }
            CP_COMMIT();
        }

        const u32 SH = SH0 + (lc & 1)*16384;

        // ---- dual GEMM: s = U x h^T (reg A),  c = FW x h^T (smem A) ----
        float sacc[4][4], cacc[4][4];
#pragma unroll
        for (int nt = 0; nt < 4; nt++)
#pragma unroll
            for (int j = 0; j < 4; j++) { sacc[nt][j] = 0.f; cacc[nt][j] = 0.f; }

#pragma unroll
        for (int ks = 0; ks < 16; ks++) {
            u32 asw = (((ks*2 + aX) ^ (rowA & 7)) << 4);
            u32 q0, q1, q2, q3;
            ldsm4(SFW + rowA*512 + asw, q0, q1, q2, q3);
#pragma unroll
            for (int ntp = 0; ntp < 2; ntp++) {
                int n = (ntp*2 + nHi)*8 + nb8;
                u32 b0, b1, b2, b3;
                ldsm4(SH + n*512 + (((ks*2 + bX) ^ (n & 7)) << 4), b0, b1, b2, b3);
                MMA(sacc[ntp*2],     au[ks][0], au[ks][1], au[ks][2], au[ks][3], b0, b1);
                MMA(cacc[ntp*2],     q0, q1, q2, q3, b0, b1);
                MMA(sacc[ntp*2 + 1], au[ks][0], au[ks][1], au[ks][2], au[ks][3], b2, b3);
                MMA(cacc[ntp*2 + 1], q0, q1, q2, q3, b2, b3);
            }
        }

        // ---- e = exp(s); rsum; ydot += e*c; stage e ----
#pragma unroll
        for (int nt = 0; nt < 4; nt++) {
            float e00 = fexp(sacc[nt][0]);
            float e01 = fexp(sacc[nt][1]);
            float e10 = fexp(sacc[nt][2]);
            float e11 = fexp(sacc[nt][3]);
            rsum0 += e00 + e01;
            rsum1 += e10 + e11;
            ydot0 = fmaf(e00, cacc[nt][0], fmaf(e01, cacc[nt][1], ydot0));
            ydot1 = fmaf(e10, cacc[nt][2], fmaf(e11, cacc[nt][3], ydot1));
            int l = nt*8 + (lane & 3)*2;
            esm[(l  )*64 + ((r0   + l    ) & 63)] = e00;
            esm[(l+1)*64 + ((r0   + l + 1) & 63)] = e01;
            esm[(l  )*64 + ((r0+8 + l    ) & 63)] = e10;
            esm[(l+1)*64 + ((r0+8 + l + 1) & 63)] = e11;
        }
        __syncthreads();

        // ---- coalesced scalar alpha stream (unnormalized e) ----
        float* ablk = ablk0 + lc*32;
        for (int i = tid; i < 64*32; i += 128) {
            int yy = i >> 5, l = i & 31;
            if (ybase + yy < Yy)
                ablk[(size_t)yy*Ll + l] = esm[l*64 + ((yy + l) & 63)];
        }
    }

    // ---- reduce rowsums and ydot across the lane quad ----
    rsum0 += __shfl_xor_sync(0xFFFFFFFFu, rsum0, 1);
    rsum0 += __shfl_xor_sync(0xFFFFFFFFu, rsum0, 2);
    rsum1 += __shfl_xor_sync(0xFFFFFFFFu, rsum1, 1);
    rsum1 += __shfl_xor_sync(0xFFFFFFFFu, rsum1, 2);
    ydot0 += __shfl_xor_sync(0xFFFFFFFFu, ydot0, 1);
    ydot0 += __shfl_xor_sync(0xFFFFFFFFu, ydot0, 2);
    ydot1 += __shfl_xor_sync(0xFFFFFFFFu, ydot1, 1);
    ydot1 += __shfl_xor_sync(0xFFFFFFFFu, ydot1, 2);
    __syncthreads();
    if ((lane & 3) == 0) { rsm[r0] = rsum0; rsm[r0 + 8] = rsum1; }

    // ---- yhat ----
    if ((lane & 3) == 0) {
        int gy0 = ybase + r0, gy1 = gy0 + 8;
        if (gy0 < Yy) out[(size_t)b*Yy + gy0] = ydot0 / rsum0 + fb[gy0];
        if (gy1 < Yy) out[(size_t)b*Yy + gy1] = ydot1 / rsum1 + fb[gy1];
    }
    __syncthreads();

    // ---- alpha rescale: alpha = e / Z (scalar, coalesced) ----
    for (int yy = 0; yy < 64; yy++) {
        int g = ybase + yy;
        if (g >= Yy) break;
        float inv = 1.f / rsm[yy];
        float* row = ablk0 + (size_t)yy*Ll;
        for (int l = tid; l < Ll; l += 128)
            row[l] *= inv;
    }
}

// ---------------------------------------------------------------------------
// K3: BCE loss, two-stage deterministic reduction
// ---------------------------------------------------------------------------
__global__ void k_loss1(const float* __restrict__ target, const float* __restrict__ out)
{
    __shared__ float red[256];
    int tid = threadIdx.x;
    float s = 0.f;
    for (int i = blockIdx.x*256 + tid; i < Bb*Yy; i += gridDim.x*256) {
        float yh = out[i];
        float t  = target[i];
        s += fmaxf(yh, 0.f) - yh*t + log1pf(__expf(-fabsf(yh)));
    }
    red[tid] = s;
    __syncthreads();
    for (int st = 128; st > 0; st >>= 1) {
        if (tid < st) red[tid] += red[tid + st];
        __syncthreads();
    }
    if (tid == 0) g_part[blockIdx.x] = red[0];
}

__global__ void k_loss2(float* __restrict__ out)
{
    __shared__ float red[128];
    int tid = threadIdx.x;
    red[tid] = (tid < 70) ? g_part[tid] : 0.f;
    __syncthreads();
    for (int st = 64; st > 0; st >>= 1) {
        if (tid < st) red[tid] += red[tid + st];
        __syncthreads();
    }
    if (tid == 0) out[Bb*Yy] = red[0] / (float)(Bb*Yy);
}

// ---------------------------------------------------------------------------
extern "C" void kernel_launch(void* const* d_in, const int* in_sizes, int n_in,
                              void* d_out, int out_size)
{
    const int*   x      = (const int*)d_in[0];
    const float* target = (const float*)d_in[1];
    const float* embW   = (const float*)d_in[2];
    const float* convw  = (const float*)d_in[3];
    const float* convb  = (const float*)d_in[4];
    const float* Uw     = (const float*)d_in[5];
    const float* fw     = (const float*)d_in[6];
    const float* fb     = (const float*)d_in[7];
    float* out = (float*)d_out;

    cudaFuncSetAttribute(k_conv, cudaFuncAttributeMaxDynamicSharedMemorySize, CSMTOT);
    cudaFuncSetAttribute(k_attn, cudaFuncAttributeMaxDynamicSharedMemorySize, SMTOT);

    k_wprep<<<(KW*Ff*120 + 255)/256, 256>>>(convw);
    k_conv<<<dim3(Ll/64, Bb), 128, CSMTOT>>>(x, embW, convb);
    k_attn<<<dim3(YT, Bb), 128, SMTOT>>>(Uw, fw, fb, out);
    k_loss1<<<70, 256>>>(target, out);
    k_loss2<<<1, 128>>>(out);
}